// round 1
// baseline (speedup 1.0000x reference)
#include <cuda_runtime.h>
#include <math.h>
#include <stdint.h>

typedef unsigned long long ull;

#define NBATCH 8
#define NPIX   4096
#define DEMB   128
#define ATT_SCALE 0.08838834764831845f   // 128^-0.5
#define BN_EPS 1e-5f

// ---------------- scratch (no allocations allowed) ----------------
// g_proj[p][b][.][.]: p=0..5 = Qa,Ka,Va,Qb,Kb,Vb. Q/K stored [d][n]; V stored [n][d].
__device__ float g_proj[(size_t)6 * NBATCH * DEMB * NPIX];   // ~100.7 MB
__device__ float g_comb[(size_t)NBATCH * 256 * NPIX];        // ~33.6 MB

// ---------------- f32x2 helpers (Blackwell packed fp32) ----------------
__device__ __forceinline__ ull f2fma(ull a, ull b, ull c) {
    ull d; asm("fma.rn.f32x2 %0,%1,%2,%3;" : "=l"(d) : "l"(a), "l"(b), "l"(c)); return d;
}
__device__ __forceinline__ ull f2mul(ull a, ull b) {
    ull d; asm("mul.rn.f32x2 %0,%1,%2;" : "=l"(d) : "l"(a), "l"(b)); return d;
}
__device__ __forceinline__ ull fpack(float lo, float hi) {
    ull r; asm("mov.b64 %0,{%1,%2};" : "=l"(r) : "f"(lo), "f"(hi)); return r;
}
__device__ __forceinline__ float2 funpack(ull v) {
    float2 r; asm("mov.b64 {%0,%1},%2;" : "=f"(r.x), "=f"(r.y) : "l"(v)); return r;
}

// ---------------- generic GEMM: Y(M,4096) = W(M,K) @ X(K,4096) + epilogue ----
// mode 0: Y[m][n] = acc + bias[m]                         (Q/K projections)
// mode 2: Yt[n][m] = acc + bias[m]   (transposed store)   (V projections)
// mode 1: Y[m][n] = relu(acc*inv[m] + shift[m])           (final proj + BN)
__global__ __launch_bounds__(256) void gemm128_kernel(
    const float* __restrict__ X, const float* __restrict__ W,
    const float* __restrict__ bias, float* __restrict__ Y,
    int K, long xstride, long ystride, int mode,
    const float* __restrict__ bng, const float* __restrict__ bnb,
    const float* __restrict__ bnm, const float* __restrict__ bnv)
{
    __shared__ float Xs[32][128];
    __shared__ float Ws[32][132];   // [kk][m], padded to reduce store conflicts

    const int tid   = threadIdx.x;
    const int nbase = blockIdx.x * 128;
    const int mbase = blockIdx.y * 128;
    const float* Xb = X + (size_t)blockIdx.z * xstride;
    float*       Yb = Y + (size_t)blockIdx.z * ystride;

    float acc[8][8];
#pragma unroll
    for (int i = 0; i < 8; i++)
#pragma unroll
        for (int j = 0; j < 8; j++) acc[i][j] = 0.f;

    const int n0 = 8 * (tid % 16);
    const int m0 = 8 * (tid / 16);

    for (int k0 = 0; k0 < K; k0 += 32) {
        // load X tile [32][128]
        {
            int r = tid / 32, c = 4 * (tid % 32);
#pragma unroll
            for (int p = 0; p < 4; p++) {
                int row = r + 8 * p;
                *(float4*)&Xs[row][c] =
                    *(const float4*)&Xb[(size_t)(k0 + row) * NPIX + nbase + c];
            }
        }
        // load W tile transposed -> Ws[kk][m]
        {
            int m = tid / 8, kk = 4 * (tid % 8);
#pragma unroll
            for (int p = 0; p < 4; p++) {
                int mm = m + 32 * p;
                float4 w = *(const float4*)&W[(size_t)(mbase + mm) * K + k0 + kk];
                Ws[kk + 0][mm] = w.x; Ws[kk + 1][mm] = w.y;
                Ws[kk + 2][mm] = w.z; Ws[kk + 3][mm] = w.w;
            }
        }
        __syncthreads();

#pragma unroll 4
        for (int kk = 0; kk < 32; kk++) {
            float4 xa = *(float4*)&Xs[kk][n0];
            float4 xb = *(float4*)&Xs[kk][n0 + 4];
            float4 wa = *(float4*)&Ws[kk][m0];
            float4 wb = *(float4*)&Ws[kk][m0 + 4];
            float xr[8] = {xa.x, xa.y, xa.z, xa.w, xb.x, xb.y, xb.z, xb.w};
            float wr[8] = {wa.x, wa.y, wa.z, wa.w, wb.x, wb.y, wb.z, wb.w};
#pragma unroll
            for (int i = 0; i < 8; i++)
#pragma unroll
                for (int j = 0; j < 8; j++) acc[i][j] = fmaf(wr[i], xr[j], acc[i][j]);
        }
        __syncthreads();
    }

    if (mode == 0) {
#pragma unroll
        for (int i = 0; i < 8; i++) {
            float bv = bias[mbase + m0 + i];
            float4 o1 = make_float4(acc[i][0] + bv, acc[i][1] + bv, acc[i][2] + bv, acc[i][3] + bv);
            float4 o2 = make_float4(acc[i][4] + bv, acc[i][5] + bv, acc[i][6] + bv, acc[i][7] + bv);
            float* dst = &Yb[(size_t)(mbase + m0 + i) * NPIX + nbase + n0];
            *(float4*)dst = o1; *(float4*)(dst + 4) = o2;
        }
    } else if (mode == 2) {
        float bv[8];
#pragma unroll
        for (int i = 0; i < 8; i++) bv[i] = bias[mbase + m0 + i];
#pragma unroll
        for (int j = 0; j < 8; j++) {
            float4 o1 = make_float4(acc[0][j] + bv[0], acc[1][j] + bv[1],
                                    acc[2][j] + bv[2], acc[3][j] + bv[3]);
            float4 o2 = make_float4(acc[4][j] + bv[4], acc[5][j] + bv[5],
                                    acc[6][j] + bv[6], acc[7][j] + bv[7]);
            float* dst = &Yb[(size_t)(nbase + n0 + j) * DEMB + mbase + m0];
            *(float4*)dst = o1; *(float4*)(dst + 4) = o2;
        }
    } else {  // mode 1: BN + ReLU
#pragma unroll
        for (int i = 0; i < 8; i++) {
            int m = mbase + m0 + i;
            float inv = bng[m] * rsqrtf(bnv[m] + BN_EPS);
            float sh  = bnb[m] - bnm[m] * inv;
            float o[8];
#pragma unroll
            for (int j = 0; j < 8; j++) o[j] = fmaxf(fmaf(acc[i][j], inv, sh), 0.f);
            float* dst = &Yb[(size_t)m * NPIX + nbase + n0];
            *(float4*)dst       = make_float4(o[0], o[1], o[2], o[3]);
            *(float4*)(dst + 4) = make_float4(o[4], o[5], o[6], o[7]);
        }
    }
}

// ---------------- flash attention: BQ=64 queries/CTA, BK=64 key tiles --------
#define BQ 64
#define BK 64
#define PS_STRIDE 68  // padded P row stride

// smem floats: Qs 128*64 + Ks 128*64 + Vs 64*128 + Ps 64*68
#define ATT_SMEM_FLOATS (128 * BQ + 128 * BK + BK * 128 + BK * PS_STRIDE)
#define ATT_SMEM_BYTES  (ATT_SMEM_FLOATS * 4)

__global__ __launch_bounds__(256) void attn_kernel(const float* __restrict__ proj,
                                                   float* __restrict__ comb)
{
    extern __shared__ float sm[];
    float* Qs = sm;                       // [d][q]  (stride BQ)
    float* Ks = Qs + 128 * BQ;            // [d][k]  (stride BK)
    float* Vs = Ks + 128 * BK;            // [k][d]  (stride 128)
    float* Ps = Vs + BK * 128;            // [k][q]  (stride 68)

    const int tid  = threadIdx.x;
    const int qt   = blockIdx.x;
    const int dir  = blockIdx.y;
    const int b    = blockIdx.z;
    const size_t PBATCH = (size_t)DEMB * NPIX;           // per-(proj,batch) block
    const size_t PPROJ  = (size_t)NBATCH * PBATCH;

    const float* Q = proj + (size_t)(dir * 3 + 0) * PPROJ + (size_t)b * PBATCH; // [d][n]
    const float* K = proj + (size_t)(dir * 3 + 1) * PPROJ + (size_t)b * PBATCH; // [d][n]
    const float* V = proj + (size_t)(dir * 3 + 2) * PPROJ + (size_t)b * PBATCH; // [n][d]
    float* Ob = comb + (size_t)b * 256 * NPIX + (size_t)dir * DEMB * NPIX;

    const int qbase = qt * BQ;
    const int qg = tid / 16, ds = tid % 16;
    const int q0 = 4 * qg, k0 = 4 * ds;

    // load Q tile once
    {
        int c4 = 4 * (tid % 16), r0 = tid / 16;
#pragma unroll
        for (int p = 0; p < 8; p++) {
            int d = r0 + 16 * p;
            *(float4*)&Qs[d * BQ + c4] = *(const float4*)&Q[(size_t)d * NPIX + qbase + c4];
        }
    }

    ull  oacc[4][4];
#pragma unroll
    for (int i = 0; i < 4; i++)
#pragma unroll
        for (int c = 0; c < 4; c++) oacc[i][c] = 0ULL;
    float mrow[4] = {-1e30f, -1e30f, -1e30f, -1e30f};
    float lrow[4] = {0.f, 0.f, 0.f, 0.f};

    for (int kt = 0; kt < NPIX / BK; kt++) {
        const int kbase = kt * BK;
        // load K tile [d][k]
        {
            int c4 = 4 * (tid % 16), r0 = tid / 16;
#pragma unroll
            for (int p = 0; p < 8; p++) {
                int d = r0 + 16 * p;
                *(float4*)&Ks[d * BK + c4] = *(const float4*)&K[(size_t)d * NPIX + kbase + c4];
            }
        }
        // load V tile [k][d]  (V already transposed in global)
        {
            int c4 = 4 * (tid % 32), r0 = tid / 32;
#pragma unroll
            for (int p = 0; p < 8; p++) {
                int k = r0 + 8 * p;
                *(float4*)&Vs[k * 128 + c4] = *(const float4*)&V[(size_t)(kbase + k) * DEMB + c4];
            }
        }
        __syncthreads();

        // scores: s[i][j] = sum_d Q[d][q0+i] * K[d][k0+j]  (f32x2, j in pairs)
        ull sacc[4][2];
#pragma unroll
        for (int i = 0; i < 4; i++) { sacc[i][0] = 0ULL; sacc[i][1] = 0ULL; }
#pragma unroll 8
        for (int d = 0; d < 128; d++) {
            float4 qv = *(float4*)&Qs[d * BQ + q0];
            float4 kv = *(float4*)&Ks[d * BK + k0];
            ull k01 = fpack(kv.x, kv.y);
            ull k23 = fpack(kv.z, kv.w);
            ull qd;
            qd = fpack(qv.x, qv.x); sacc[0][0] = f2fma(qd, k01, sacc[0][0]); sacc[0][1] = f2fma(qd, k23, sacc[0][1]);
            qd = fpack(qv.y, qv.y); sacc[1][0] = f2fma(qd, k01, sacc[1][0]); sacc[1][1] = f2fma(qd, k23, sacc[1][1]);
            qd = fpack(qv.z, qv.z); sacc[2][0] = f2fma(qd, k01, sacc[2][0]); sacc[2][1] = f2fma(qd, k23, sacc[2][1]);
            qd = fpack(qv.w, qv.w); sacc[3][0] = f2fma(qd, k01, sacc[3][0]); sacc[3][1] = f2fma(qd, k23, sacc[3][1]);
        }

        // online softmax over the 16-lane row group (lanes share tid/16)
        float pv[4][4], corr[4];
#pragma unroll
        for (int i = 0; i < 4; i++) {
            float2 a = funpack(sacc[i][0]);
            float2 c2 = funpack(sacc[i][1]);
            pv[i][0] = a.x * ATT_SCALE; pv[i][1] = a.y * ATT_SCALE;
            pv[i][2] = c2.x * ATT_SCALE; pv[i][3] = c2.y * ATT_SCALE;
        }
#pragma unroll
        for (int i = 0; i < 4; i++) {
            float mx = fmaxf(fmaxf(pv[i][0], pv[i][1]), fmaxf(pv[i][2], pv[i][3]));
#pragma unroll
            for (int off = 1; off < 16; off <<= 1)
                mx = fmaxf(mx, __shfl_xor_sync(0xffffffffu, mx, off));
            float mn = fmaxf(mrow[i], mx);
            corr[i] = __expf(mrow[i] - mn);
            mrow[i] = mn;
            float rs = 0.f;
#pragma unroll
            for (int j = 0; j < 4; j++) { pv[i][j] = __expf(pv[i][j] - mn); rs += pv[i][j]; }
#pragma unroll
            for (int off = 1; off < 16; off <<= 1)
                rs += __shfl_xor_sync(0xffffffffu, rs, off);
            lrow[i] = lrow[i] * corr[i] + rs;
        }
        // rescale O accumulators
#pragma unroll
        for (int i = 0; i < 4; i++) {
            ull cd = fpack(corr[i], corr[i]);
#pragma unroll
            for (int c = 0; c < 4; c++) oacc[i][c] = f2mul(oacc[i][c], cd);
        }
        // publish P tile: Ps[k][q]
#pragma unroll
        for (int c = 0; c < 4; c++) {
            *(float4*)&Ps[(k0 + c) * PS_STRIDE + q0] =
                make_float4(pv[0][c], pv[1][c], pv[2][c], pv[3][c]);
        }
        __syncthreads();

        // O accumulate: thread owns d in [4ds,4ds+4) U [64+4ds,64+4ds+4)
#pragma unroll 4
        for (int k = 0; k < BK; k++) {
            float4 p4 = *(float4*)&Ps[k * PS_STRIDE + q0];
            float4 va = *(float4*)&Vs[k * 128 + 4 * ds];
            float4 vb = *(float4*)&Vs[k * 128 + 64 + 4 * ds];
            ull va01 = fpack(va.x, va.y), va23 = fpack(va.z, va.w);
            ull vb01 = fpack(vb.x, vb.y), vb23 = fpack(vb.z, vb.w);
            float pr[4] = {p4.x, p4.y, p4.z, p4.w};
#pragma unroll
            for (int i = 0; i < 4; i++) {
                ull pd = fpack(pr[i], pr[i]);
                oacc[i][0] = f2fma(pd, va01, oacc[i][0]);
                oacc[i][1] = f2fma(pd, va23, oacc[i][1]);
                oacc[i][2] = f2fma(pd, vb01, oacc[i][2]);
                oacc[i][3] = f2fma(pd, vb23, oacc[i][3]);
            }
        }
        __syncthreads();
    }

    // epilogue: O /= l, store to comb[d][n]
    float o[4][8];
#pragma unroll
    for (int i = 0; i < 4; i++) {
        float il = 1.0f / lrow[i];
#pragma unroll
        for (int c = 0; c < 4; c++) {
            float2 t = funpack(oacc[i][c]);
            o[i][2 * c]     = t.x * il;
            o[i][2 * c + 1] = t.y * il;
        }
    }
#pragma unroll
    for (int cc = 0; cc < 8; cc++) {
        int d = (cc < 4) ? (4 * ds + cc) : (64 + 4 * ds + (cc - 4));
        float4 ov = make_float4(o[0][cc], o[1][cc], o[2][cc], o[3][cc]);
        *(float4*)&Ob[(size_t)d * NPIX + qbase + q0] = ov;
    }
}

// ---------------- launch ----------------
extern "C" void kernel_launch(void* const* d_in, const int* in_sizes, int n_in,
                              void* d_out, int out_size)
{
    (void)in_sizes; (void)n_in; (void)out_size;
    const float* f_rgb   = (const float*)d_in[0];
    const float* f_pl    = (const float*)d_in[1];
    const float* w_q_rgb = (const float*)d_in[2];
    const float* b_q_rgb = (const float*)d_in[3];
    const float* w_k_pl  = (const float*)d_in[4];
    const float* b_k_pl  = (const float*)d_in[5];
    const float* w_v_pl  = (const float*)d_in[6];
    const float* b_v_pl  = (const float*)d_in[7];
    const float* w_q_pl  = (const float*)d_in[8];
    const float* b_q_pl  = (const float*)d_in[9];
    const float* w_k_rgb = (const float*)d_in[10];
    const float* b_k_rgb = (const float*)d_in[11];
    const float* w_v_rgb = (const float*)d_in[12];
    const float* b_v_rgb = (const float*)d_in[13];
    const float* w_proj  = (const float*)d_in[14];
    const float* bn_g    = (const float*)d_in[15];
    const float* bn_b    = (const float*)d_in[16];
    const float* bn_m    = (const float*)d_in[17];
    const float* bn_v    = (const float*)d_in[18];

    float* projp = nullptr; float* combp = nullptr;
    cudaGetSymbolAddress((void**)&projp, g_proj);
    cudaGetSymbolAddress((void**)&combp, g_comb);

    const long xs_in  = 256L * NPIX;          // batch stride of f_* / comb
    const long ys_pr  = (long)DEMB * NPIX;    // batch stride of proj outputs
    const size_t PPROJ = (size_t)NBATCH * DEMB * NPIX;

    struct { const float* x; const float* w; const float* bias; int mode; } P[6] = {
        { f_rgb, w_q_rgb, b_q_rgb, 0 },   // 0: Q_a
        { f_pl,  w_k_pl,  b_k_pl,  0 },   // 1: K_a
        { f_pl,  w_v_pl,  b_v_pl,  2 },   // 2: V_a (transposed [n][d])
        { f_pl,  w_q_pl,  b_q_pl,  0 },   // 3: Q_b
        { f_rgb, w_k_rgb, b_k_rgb, 0 },   // 4: K_b
        { f_rgb, w_v_rgb, b_v_rgb, 2 },   // 5: V_b (transposed [n][d])
    };

    dim3 blk(256);
    dim3 gp(32, 1, NBATCH);
    for (int p = 0; p < 6; p++) {
        gemm128_kernel<<<gp, blk>>>(P[p].x, P[p].w, P[p].bias,
                                    projp + (size_t)p * PPROJ,
                                    256, xs_in, ys_pr, P[p].mode,
                                    nullptr, nullptr, nullptr, nullptr);
    }

    cudaFuncSetAttribute(attn_kernel, cudaFuncAttributeMaxDynamicSharedMemorySize,
                         ATT_SMEM_BYTES);
    attn_kernel<<<dim3(NPIX / BQ, 2, NBATCH), blk, ATT_SMEM_BYTES>>>(projp, combp);

    gemm128_kernel<<<dim3(32, 2, NBATCH), blk>>>(combp, w_proj, nullptr,
                                                 (float*)d_out,
                                                 256, xs_in, 256L * NPIX, 1,
                                                 bn_g, bn_b, bn_m, bn_v);
}

// round 2
// speedup vs baseline: 1.0013x; 1.0013x over previous
#include <cuda_runtime.h>
#include <math.h>
#include <stdint.h>

typedef unsigned long long ull;

#define NBATCH 8
#define NPIX   4096
#define DEMB   128
#define ATT_SCALE 0.08838834764831845f   // 128^-0.5
#define BN_EPS 1e-5f

// ---------------- scratch (no allocations allowed) ----------------
// g_proj[p][b][.][.]: p=0..5 = Qa,Ka,Va,Qb,Kb,Vb. Q/K stored [d][n]; V stored [n][d].
__device__ float g_proj[(size_t)6 * NBATCH * DEMB * NPIX];   // ~100.7 MB
__device__ float g_comb[(size_t)NBATCH * 256 * NPIX];        // ~33.6 MB

// ---------------- f32x2 helpers (Blackwell packed fp32) ----------------
__device__ __forceinline__ ull f2fma(ull a, ull b, ull c) {
    ull d; asm("fma.rn.f32x2 %0,%1,%2,%3;" : "=l"(d) : "l"(a), "l"(b), "l"(c)); return d;
}
__device__ __forceinline__ ull f2mul(ull a, ull b) {
    ull d; asm("mul.rn.f32x2 %0,%1,%2;" : "=l"(d) : "l"(a), "l"(b)); return d;
}
__device__ __forceinline__ ull fpack(float lo, float hi) {
    ull r; asm("mov.b64 %0,{%1,%2};" : "=l"(r) : "f"(lo), "f"(hi)); return r;
}
__device__ __forceinline__ float2 funpack(ull v) {
    float2 r; asm("mov.b64 {%0,%1},%2;" : "=f"(r.x), "=f"(r.y) : "l"(v)); return r;
}

// ---------------- generic GEMM: Y(M,4096) = W(M,K) @ X(K,4096) + epilogue ----
// mode 0: Y[m][n] = acc + bias[m]                         (Q/K projections)
// mode 2: Yt[n][m] = acc + bias[m]   (transposed store)   (V projections)
// mode 1: Y[m][n] = relu(acc*inv[m] + shift[m])           (final proj + BN)
__global__ __launch_bounds__(256) void gemm128_kernel(
    const float* __restrict__ X, const float* __restrict__ W,
    const float* __restrict__ bias, float* __restrict__ Y,
    int K, long xstride, long ystride, int mode,
    const float* __restrict__ bng, const float* __restrict__ bnb,
    const float* __restrict__ bnm, const float* __restrict__ bnv)
{
    __shared__ float Xs[32][128];
    __shared__ float Ws[32][132];   // [kk][m], padded to reduce store conflicts

    const int tid   = threadIdx.x;
    const int nbase = blockIdx.x * 128;
    const int mbase = blockIdx.y * 128;
    const float* Xb = X + (size_t)blockIdx.z * xstride;
    float*       Yb = Y + (size_t)blockIdx.z * ystride;

    float acc[8][8];
#pragma unroll
    for (int i = 0; i < 8; i++)
#pragma unroll
        for (int j = 0; j < 8; j++) acc[i][j] = 0.f;

    const int n0 = 8 * (tid % 16);
    const int m0 = 8 * (tid / 16);

    for (int k0 = 0; k0 < K; k0 += 32) {
        // load X tile [32][128]
        {
            int r = tid / 32, c = 4 * (tid % 32);
#pragma unroll
            for (int p = 0; p < 4; p++) {
                int row = r + 8 * p;
                *(float4*)&Xs[row][c] =
                    *(const float4*)&Xb[(size_t)(k0 + row) * NPIX + nbase + c];
            }
        }
        // load W tile transposed -> Ws[kk][m]
        {
            int m = tid / 8, kk = 4 * (tid % 8);
#pragma unroll
            for (int p = 0; p < 4; p++) {
                int mm = m + 32 * p;
                float4 w = *(const float4*)&W[(size_t)(mbase + mm) * K + k0 + kk];
                Ws[kk + 0][mm] = w.x; Ws[kk + 1][mm] = w.y;
                Ws[kk + 2][mm] = w.z; Ws[kk + 3][mm] = w.w;
            }
        }
        __syncthreads();

#pragma unroll 4
        for (int kk = 0; kk < 32; kk++) {
            float4 xa = *(float4*)&Xs[kk][n0];
            float4 xb = *(float4*)&Xs[kk][n0 + 4];
            float4 wa = *(float4*)&Ws[kk][m0];
            float4 wb = *(float4*)&Ws[kk][m0 + 4];
            float xr[8] = {xa.x, xa.y, xa.z, xa.w, xb.x, xb.y, xb.z, xb.w};
            float wr[8] = {wa.x, wa.y, wa.z, wa.w, wb.x, wb.y, wb.z, wb.w};
#pragma unroll
            for (int i = 0; i < 8; i++)
#pragma unroll
                for (int j = 0; j < 8; j++) acc[i][j] = fmaf(wr[i], xr[j], acc[i][j]);
        }
        __syncthreads();
    }

    if (mode == 0) {
#pragma unroll
        for (int i = 0; i < 8; i++) {
            float bv = bias[mbase + m0 + i];
            float4 o1 = make_float4(acc[i][0] + bv, acc[i][1] + bv, acc[i][2] + bv, acc[i][3] + bv);
            float4 o2 = make_float4(acc[i][4] + bv, acc[i][5] + bv, acc[i][6] + bv, acc[i][7] + bv);
            float* dst = &Yb[(size_t)(mbase + m0 + i) * NPIX + nbase + n0];
            *(float4*)dst = o1; *(float4*)(dst + 4) = o2;
        }
    } else if (mode == 2) {
        float bv[8];
#pragma unroll
        for (int i = 0; i < 8; i++) bv[i] = bias[mbase + m0 + i];
#pragma unroll
        for (int j = 0; j < 8; j++) {
            float4 o1 = make_float4(acc[0][j] + bv[0], acc[1][j] + bv[1],
                                    acc[2][j] + bv[2], acc[3][j] + bv[3]);
            float4 o2 = make_float4(acc[4][j] + bv[4], acc[5][j] + bv[5],
                                    acc[6][j] + bv[6], acc[7][j] + bv[7]);
            float* dst = &Yb[(size_t)(nbase + n0 + j) * DEMB + mbase + m0];
            *(float4*)dst = o1; *(float4*)(dst + 4) = o2;
        }
    } else {  // mode 1: BN + ReLU
#pragma unroll
        for (int i = 0; i < 8; i++) {
            int m = mbase + m0 + i;
            float inv = bng[m] * rsqrtf(bnv[m] + BN_EPS);
            float sh  = bnb[m] - bnm[m] * inv;
            float o[8];
#pragma unroll
            for (int j = 0; j < 8; j++) o[j] = fmaxf(fmaf(acc[i][j], inv, sh), 0.f);
            float* dst = &Yb[(size_t)m * NPIX + nbase + n0];
            *(float4*)dst       = make_float4(o[0], o[1], o[2], o[3]);
            *(float4*)(dst + 4) = make_float4(o[4], o[5], o[6], o[7]);
        }
    }
}

// ---------------- flash attention: BQ=64 queries/CTA, BK=64 key tiles --------
#define BQ 64
#define BK 64
#define PS_STRIDE 68  // padded P row stride

// smem floats: Qs 128*64 + Ks 128*64 + Vs 64*128 + Ps 64*68
#define ATT_SMEM_FLOATS (128 * BQ + 128 * BK + BK * 128 + BK * PS_STRIDE)
#define ATT_SMEM_BYTES  (ATT_SMEM_FLOATS * 4)

__global__ __launch_bounds__(256) void attn_kernel(const float* __restrict__ proj,
                                                   float* __restrict__ comb)
{
    extern __shared__ float sm[];
    float* Qs = sm;                       // [d][q]  (stride BQ)
    float* Ks = Qs + 128 * BQ;            // [d][k]  (stride BK)
    float* Vs = Ks + 128 * BK;            // [k][d]  (stride 128)
    float* Ps = Vs + BK * 128;            // [k][q]  (stride 68)

    const int tid  = threadIdx.x;
    const int qt   = blockIdx.x;
    const int dir  = blockIdx.y;
    const int b    = blockIdx.z;
    const size_t PBATCH = (size_t)DEMB * NPIX;           // per-(proj,batch) block
    const size_t PPROJ  = (size_t)NBATCH * PBATCH;

    const float* Q = proj + (size_t)(dir * 3 + 0) * PPROJ + (size_t)b * PBATCH; // [d][n]
    const float* K = proj + (size_t)(dir * 3 + 1) * PPROJ + (size_t)b * PBATCH; // [d][n]
    const float* V = proj + (size_t)(dir * 3 + 2) * PPROJ + (size_t)b * PBATCH; // [n][d]
    float* Ob = comb + (size_t)b * 256 * NPIX + (size_t)dir * DEMB * NPIX;

    const int qbase = qt * BQ;
    const int qg = tid / 16, ds = tid % 16;
    const int q0 = 4 * qg, k0 = 4 * ds;

    // load Q tile once
    {
        int c4 = 4 * (tid % 16), r0 = tid / 16;
#pragma unroll
        for (int p = 0; p < 8; p++) {
            int d = r0 + 16 * p;
            *(float4*)&Qs[d * BQ + c4] = *(const float4*)&Q[(size_t)d * NPIX + qbase + c4];
        }
    }

    ull  oacc[4][4];
#pragma unroll
    for (int i = 0; i < 4; i++)
#pragma unroll
        for (int c = 0; c < 4; c++) oacc[i][c] = 0ULL;
    float mrow[4] = {-1e30f, -1e30f, -1e30f, -1e30f};
    float lrow[4] = {0.f, 0.f, 0.f, 0.f};

    for (int kt = 0; kt < NPIX / BK; kt++) {
        const int kbase = kt * BK;
        // load K tile [d][k]
        {
            int c4 = 4 * (tid % 16), r0 = tid / 16;
#pragma unroll
            for (int p = 0; p < 8; p++) {
                int d = r0 + 16 * p;
                *(float4*)&Ks[d * BK + c4] = *(const float4*)&K[(size_t)d * NPIX + kbase + c4];
            }
        }
        // load V tile [k][d]  (V already transposed in global)
        {
            int c4 = 4 * (tid % 32), r0 = tid / 32;
#pragma unroll
            for (int p = 0; p < 8; p++) {
                int k = r0 + 8 * p;
                *(float4*)&Vs[k * 128 + c4] = *(const float4*)&V[(size_t)(kbase + k) * DEMB + c4];
            }
        }
        __syncthreads();

        // scores: s[i][j] = sum_d Q[d][q0+i] * K[d][k0+j]  (f32x2, j in pairs)
        ull sacc[4][2];
#pragma unroll
        for (int i = 0; i < 4; i++) { sacc[i][0] = 0ULL; sacc[i][1] = 0ULL; }
#pragma unroll 8
        for (int d = 0; d < 128; d++) {
            float4 qv = *(float4*)&Qs[d * BQ + q0];
            float4 kv = *(float4*)&Ks[d * BK + k0];
            ull k01 = fpack(kv.x, kv.y);
            ull k23 = fpack(kv.z, kv.w);
            ull qd;
            qd = fpack(qv.x, qv.x); sacc[0][0] = f2fma(qd, k01, sacc[0][0]); sacc[0][1] = f2fma(qd, k23, sacc[0][1]);
            qd = fpack(qv.y, qv.y); sacc[1][0] = f2fma(qd, k01, sacc[1][0]); sacc[1][1] = f2fma(qd, k23, sacc[1][1]);
            qd = fpack(qv.z, qv.z); sacc[2][0] = f2fma(qd, k01, sacc[2][0]); sacc[2][1] = f2fma(qd, k23, sacc[2][1]);
            qd = fpack(qv.w, qv.w); sacc[3][0] = f2fma(qd, k01, sacc[3][0]); sacc[3][1] = f2fma(qd, k23, sacc[3][1]);
        }

        // online softmax over the 16-lane row group (lanes share tid/16)
        float pv[4][4], corr[4];
#pragma unroll
        for (int i = 0; i < 4; i++) {
            float2 a = funpack(sacc[i][0]);
            float2 c2 = funpack(sacc[i][1]);
            pv[i][0] = a.x * ATT_SCALE; pv[i][1] = a.y * ATT_SCALE;
            pv[i][2] = c2.x * ATT_SCALE; pv[i][3] = c2.y * ATT_SCALE;
        }
#pragma unroll
        for (int i = 0; i < 4; i++) {
            float mx = fmaxf(fmaxf(pv[i][0], pv[i][1]), fmaxf(pv[i][2], pv[i][3]));
#pragma unroll
            for (int off = 1; off < 16; off <<= 1)
                mx = fmaxf(mx, __shfl_xor_sync(0xffffffffu, mx, off));
            float mn = fmaxf(mrow[i], mx);
            corr[i] = __expf(mrow[i] - mn);
            mrow[i] = mn;
            float rs = 0.f;
#pragma unroll
            for (int j = 0; j < 4; j++) { pv[i][j] = __expf(pv[i][j] - mn); rs += pv[i][j]; }
#pragma unroll
            for (int off = 1; off < 16; off <<= 1)
                rs += __shfl_xor_sync(0xffffffffu, rs, off);
            lrow[i] = lrow[i] * corr[i] + rs;
        }
        // rescale O accumulators
#pragma unroll
        for (int i = 0; i < 4; i++) {
            ull cd = fpack(corr[i], corr[i]);
#pragma unroll
            for (int c = 0; c < 4; c++) oacc[i][c] = f2mul(oacc[i][c], cd);
        }
        // publish P tile: Ps[k][q]
#pragma unroll
        for (int c = 0; c < 4; c++) {
            *(float4*)&Ps[(k0 + c) * PS_STRIDE + q0] =
                make_float4(pv[0][c], pv[1][c], pv[2][c], pv[3][c]);
        }
        __syncthreads();

        // O accumulate: thread owns d in [4ds,4ds+4) U [64+4ds,64+4ds+4)
#pragma unroll 4
        for (int k = 0; k < BK; k++) {
            float4 p4 = *(float4*)&Ps[k * PS_STRIDE + q0];
            float4 va = *(float4*)&Vs[k * 128 + 4 * ds];
            float4 vb = *(float4*)&Vs[k * 128 + 64 + 4 * ds];
            ull va01 = fpack(va.x, va.y), va23 = fpack(va.z, va.w);
            ull vb01 = fpack(vb.x, vb.y), vb23 = fpack(vb.z, vb.w);
            float pr[4] = {p4.x, p4.y, p4.z, p4.w};
#pragma unroll
            for (int i = 0; i < 4; i++) {
                ull pd = fpack(pr[i], pr[i]);
                oacc[i][0] = f2fma(pd, va01, oacc[i][0]);
                oacc[i][1] = f2fma(pd, va23, oacc[i][1]);
                oacc[i][2] = f2fma(pd, vb01, oacc[i][2]);
                oacc[i][3] = f2fma(pd, vb23, oacc[i][3]);
            }
        }
        __syncthreads();
    }

    // epilogue: O /= l, store to comb[d][n]
    float o[4][8];
#pragma unroll
    for (int i = 0; i < 4; i++) {
        float il = 1.0f / lrow[i];
#pragma unroll
        for (int c = 0; c < 4; c++) {
            float2 t = funpack(oacc[i][c]);
            o[i][2 * c]     = t.x * il;
            o[i][2 * c + 1] = t.y * il;
        }
    }
#pragma unroll
    for (int cc = 0; cc < 8; cc++) {
        int d = (cc < 4) ? (4 * ds + cc) : (64 + 4 * ds + (cc - 4));
        float4 ov = make_float4(o[0][cc], o[1][cc], o[2][cc], o[3][cc]);
        *(float4*)&Ob[(size_t)d * NPIX + qbase + q0] = ov;
    }
}

// ---------------- launch ----------------
extern "C" void kernel_launch(void* const* d_in, const int* in_sizes, int n_in,
                              void* d_out, int out_size)
{
    (void)in_sizes; (void)n_in; (void)out_size;
    const float* f_rgb   = (const float*)d_in[0];
    const float* f_pl    = (const float*)d_in[1];
    const float* w_q_rgb = (const float*)d_in[2];
    const float* b_q_rgb = (const float*)d_in[3];
    const float* w_k_pl  = (const float*)d_in[4];
    const float* b_k_pl  = (const float*)d_in[5];
    const float* w_v_pl  = (const float*)d_in[6];
    const float* b_v_pl  = (const float*)d_in[7];
    const float* w_q_pl  = (const float*)d_in[8];
    const float* b_q_pl  = (const float*)d_in[9];
    const float* w_k_rgb = (const float*)d_in[10];
    const float* b_k_rgb = (const float*)d_in[11];
    const float* w_v_rgb = (const float*)d_in[12];
    const float* b_v_rgb = (const float*)d_in[13];
    const float* w_proj  = (const float*)d_in[14];
    const float* bn_g    = (const float*)d_in[15];
    const float* bn_b    = (const float*)d_in[16];
    const float* bn_m    = (const float*)d_in[17];
    const float* bn_v    = (const float*)d_in[18];

    float* projp = nullptr; float* combp = nullptr;
    cudaGetSymbolAddress((void**)&projp, g_proj);
    cudaGetSymbolAddress((void**)&combp, g_comb);

    const long xs_in  = 256L * NPIX;          // batch stride of f_* / comb
    const long ys_pr  = (long)DEMB * NPIX;    // batch stride of proj outputs
    const size_t PPROJ = (size_t)NBATCH * DEMB * NPIX;

    struct { const float* x; const float* w; const float* bias; int mode; } P[6] = {
        { f_rgb, w_q_rgb, b_q_rgb, 0 },   // 0: Q_a
        { f_pl,  w_k_pl,  b_k_pl,  0 },   // 1: K_a
        { f_pl,  w_v_pl,  b_v_pl,  2 },   // 2: V_a (transposed [n][d])
        { f_pl,  w_q_pl,  b_q_pl,  0 },   // 3: Q_b
        { f_rgb, w_k_rgb, b_k_rgb, 0 },   // 4: K_b
        { f_rgb, w_v_rgb, b_v_rgb, 2 },   // 5: V_b (transposed [n][d])
    };

    dim3 blk(256);
    dim3 gp(32, 1, NBATCH);
    for (int p = 0; p < 6; p++) {
        gemm128_kernel<<<gp, blk>>>(P[p].x, P[p].w, P[p].bias,
                                    projp + (size_t)p * PPROJ,
                                    256, xs_in, ys_pr, P[p].mode,
                                    nullptr, nullptr, nullptr, nullptr);
    }

    cudaFuncSetAttribute(attn_kernel, cudaFuncAttributeMaxDynamicSharedMemorySize,
                         ATT_SMEM_BYTES);
    attn_kernel<<<dim3(NPIX / BQ, 2, NBATCH), blk, ATT_SMEM_BYTES>>>(projp, combp);

    gemm128_kernel<<<dim3(32, 2, NBATCH), blk>>>(combp, w_proj, nullptr,
                                                 (float*)d_out,
                                                 256, xs_in, 256L * NPIX, 1,
                                                 bn_g, bn_b, bn_m, bn_v);
}

// round 4
// speedup vs baseline: 1.9728x; 1.9703x over previous
#include <cuda_runtime.h>
#include <cuda_bf16.h>
#include <stdint.h>
#include <math.h>

#define NBATCH 8
#define NPIX   4096
#define DEMB   128
#define ATT_SCALE 0.08838834764831845f
#define BN_EPS 1e-5f

// bf16 planes: index (dir*6+kind), kind: 0 Qhi,1 Qlo,2 Khi,3 Klo,4 Vhi,5 Vlo
// Q,K planes stored [n][d] (d contiguous); V planes [d][n] (n contiguous).
__device__ __nv_bfloat16 g_bf[(size_t)12 * NBATCH * DEMB * NPIX];
__device__ float g_comb[(size_t)NBATCH * 256 * NPIX];

// ------------------------------------------------------------- helpers -----
__device__ __forceinline__ uint32_t smem_u32(const void* p) {
    uint32_t a;
    asm("{ .reg .u64 t; cvta.to.shared.u64 t, %1; cvt.u32.u64 %0, t; }" : "=r"(a) : "l"(p));
    return a;
}
__device__ __forceinline__ uint32_t pk(__nv_bfloat16 a, __nv_bfloat16 b) {
    __nv_bfloat162 t(a, b);
    return *reinterpret_cast<uint32_t*>(&t);
}
__device__ __forceinline__ uint32_t pkf(float a, float b) {
    return pk(__float2bfloat16(a), __float2bfloat16(b));
}
__device__ __forceinline__ void mma_bf16(float c[4], const uint32_t a[4],
                                         uint32_t b0, uint32_t b1) {
    asm volatile("mma.sync.aligned.m16n8k16.row.col.f32.bf16.bf16.f32 "
        "{%0,%1,%2,%3}, {%4,%5,%6,%7}, {%8,%9}, {%0,%1,%2,%3};"
        : "+f"(c[0]), "+f"(c[1]), "+f"(c[2]), "+f"(c[3])
        : "r"(a[0]), "r"(a[1]), "r"(a[2]), "r"(a[3]), "r"(b0), "r"(b1));
}
__device__ __forceinline__ void ldsm4(uint32_t r[4], uint32_t addr) {
    asm volatile("ldmatrix.sync.aligned.m8n8.x4.shared.b16 {%0,%1,%2,%3}, [%4];"
        : "=r"(r[0]), "=r"(r[1]), "=r"(r[2]), "=r"(r[3]) : "r"(addr));
}

// ---------------- projection GEMM: Y(128,4096) = W(128,256)@X(256,4096)+b ---
__global__ __launch_bounds__(256) void proj_kernel(
    const float* __restrict__ X, const float* __restrict__ W,
    const float* __restrict__ bias,
    __nv_bfloat16* __restrict__ Yhi, __nv_bfloat16* __restrict__ Ylo,
    float scale, int vmode)
{
    __shared__ float Xs[32][128];
    __shared__ float Ws[32][132];
    const int tid = threadIdx.x;
    const int nbase = blockIdx.x * 128;
    const float* Xb = X + (size_t)blockIdx.z * 256 * NPIX;
    __nv_bfloat16* Yh = Yhi + (size_t)blockIdx.z * DEMB * NPIX;
    __nv_bfloat16* Yl = Ylo + (size_t)blockIdx.z * DEMB * NPIX;

    float acc[8][8];
#pragma unroll
    for (int i = 0; i < 8; i++)
#pragma unroll
        for (int j = 0; j < 8; j++) acc[i][j] = 0.f;
    const int n0 = 8 * (tid % 16), m0 = 8 * (tid / 16);

    for (int k0 = 0; k0 < 256; k0 += 32) {
        {
            int r = tid / 32, c = 4 * (tid % 32);
#pragma unroll
            for (int p = 0; p < 4; p++)
                *(float4*)&Xs[r + 8 * p][c] =
                    *(const float4*)&Xb[(size_t)(k0 + r + 8 * p) * NPIX + nbase + c];
        }
        {
            int m = tid / 8, kk = 4 * (tid % 8);
#pragma unroll
            for (int p = 0; p < 4; p++) {
                int mm = m + 32 * p;
                float4 w = *(const float4*)&W[(size_t)mm * 256 + k0 + kk];
                Ws[kk + 0][mm] = w.x; Ws[kk + 1][mm] = w.y;
                Ws[kk + 2][mm] = w.z; Ws[kk + 3][mm] = w.w;
            }
        }
        __syncthreads();
#pragma unroll 4
        for (int kk = 0; kk < 32; kk++) {
            float4 xa = *(float4*)&Xs[kk][n0];
            float4 xb = *(float4*)&Xs[kk][n0 + 4];
            float4 wa = *(float4*)&Ws[kk][m0];
            float4 wb = *(float4*)&Ws[kk][m0 + 4];
            float xr[8] = {xa.x, xa.y, xa.z, xa.w, xb.x, xb.y, xb.z, xb.w};
            float wr[8] = {wa.x, wa.y, wa.z, wa.w, wb.x, wb.y, wb.z, wb.w};
#pragma unroll
            for (int i = 0; i < 8; i++)
#pragma unroll
                for (int j = 0; j < 8; j++) acc[i][j] = fmaf(wr[i], xr[j], acc[i][j]);
        }
        __syncthreads();
    }

    float bv[8];
#pragma unroll
    for (int i = 0; i < 8; i++) bv[i] = bias[m0 + i];

    if (vmode == 0) {  // [n][d]
#pragma unroll
        for (int j = 0; j < 8; j++) {
            size_t row = (size_t)(nbase + n0 + j) * DEMB;
#pragma unroll
            for (int i2 = 0; i2 < 4; i2++) {
                float f0 = (acc[2 * i2][j] + bv[2 * i2]) * scale;
                float f1 = (acc[2 * i2 + 1][j] + bv[2 * i2 + 1]) * scale;
                __nv_bfloat16 h0 = __float2bfloat16(f0), h1 = __float2bfloat16(f1);
                ((uint32_t*)&Yh[row])[m0 / 2 + i2] = pk(h0, h1);
                ((uint32_t*)&Yl[row])[m0 / 2 + i2] =
                    pk(__float2bfloat16(f0 - __bfloat162float(h0)),
                       __float2bfloat16(f1 - __bfloat162float(h1)));
            }
        }
    } else {  // [d][n]
#pragma unroll
        for (int i = 0; i < 8; i++) {
            size_t row = (size_t)(m0 + i) * NPIX;
#pragma unroll
            for (int j2 = 0; j2 < 4; j2++) {
                float f0 = acc[i][2 * j2] + bv[i];
                float f1 = acc[i][2 * j2 + 1] + bv[i];
                __nv_bfloat16 h0 = __float2bfloat16(f0), h1 = __float2bfloat16(f1);
                ((uint32_t*)&Yh[row])[(nbase + n0) / 2 + j2] = pk(h0, h1);
                ((uint32_t*)&Yl[row])[(nbase + n0) / 2 + j2] =
                    pk(__float2bfloat16(f0 - __bfloat162float(h0)),
                       __float2bfloat16(f1 - __bfloat162float(h1)));
            }
        }
    }
}

// ---------------- final GEMM: out = relu(BN(W(256,256)@comb)) ---------------
__global__ __launch_bounds__(256) void final_kernel(
    const float* __restrict__ X, const float* __restrict__ W, float* __restrict__ Y,
    const float* __restrict__ bng, const float* __restrict__ bnb,
    const float* __restrict__ bnm, const float* __restrict__ bnv)
{
    __shared__ float Xs[32][128];
    __shared__ float Ws[32][132];
    const int tid = threadIdx.x;
    const int nbase = blockIdx.x * 128;
    const int mbase = blockIdx.y * 128;
    const float* Xb = X + (size_t)blockIdx.z * 256 * NPIX;
    float* Yb = Y + (size_t)blockIdx.z * 256 * NPIX;

    float acc[8][8];
#pragma unroll
    for (int i = 0; i < 8; i++)
#pragma unroll
        for (int j = 0; j < 8; j++) acc[i][j] = 0.f;
    const int n0 = 8 * (tid % 16), m0 = 8 * (tid / 16);

    for (int k0 = 0; k0 < 256; k0 += 32) {
        {
            int r = tid / 32, c = 4 * (tid % 32);
#pragma unroll
            for (int p = 0; p < 4; p++)
                *(float4*)&Xs[r + 8 * p][c] =
                    *(const float4*)&Xb[(size_t)(k0 + r + 8 * p) * NPIX + nbase + c];
        }
        {
            int m = tid / 8, kk = 4 * (tid % 8);
#pragma unroll
            for (int p = 0; p < 4; p++) {
                int mm = m + 32 * p;
                float4 w = *(const float4*)&W[(size_t)(mbase + mm) * 256 + k0 + kk];
                Ws[kk + 0][mm] = w.x; Ws[kk + 1][mm] = w.y;
                Ws[kk + 2][mm] = w.z; Ws[kk + 3][mm] = w.w;
            }
        }
        __syncthreads();
#pragma unroll 4
        for (int kk = 0; kk < 32; kk++) {
            float4 xa = *(float4*)&Xs[kk][n0];
            float4 xb = *(float4*)&Xs[kk][n0 + 4];
            float4 wa = *(float4*)&Ws[kk][m0];
            float4 wb = *(float4*)&Ws[kk][m0 + 4];
            float xr[8] = {xa.x, xa.y, xa.z, xa.w, xb.x, xb.y, xb.z, xb.w};
            float wr[8] = {wa.x, wa.y, wa.z, wa.w, wb.x, wb.y, wb.z, wb.w};
#pragma unroll
            for (int i = 0; i < 8; i++)
#pragma unroll
                for (int j = 0; j < 8; j++) acc[i][j] = fmaf(wr[i], xr[j], acc[i][j]);
        }
        __syncthreads();
    }
#pragma unroll
    for (int i = 0; i < 8; i++) {
        int m = mbase + m0 + i;
        float inv = bng[m] * rsqrtf(bnv[m] + BN_EPS);
        float sh = bnb[m] - bnm[m] * inv;
        float o[8];
#pragma unroll
        for (int j = 0; j < 8; j++) o[j] = fmaxf(fmaf(acc[i][j], inv, sh), 0.f);
        float* dst = &Yb[(size_t)m * NPIX + nbase + n0];
        *(float4*)dst = make_float4(o[0], o[1], o[2], o[3]);
        *(float4*)(dst + 4) = make_float4(o[4], o[5], o[6], o[7]);
    }
}

// ---------------- warp-MMA flash attention ----------------------------------
// CTA: 128 queries, 256 threads (8 warps x m16 query slab, full 128-key tiles).
// SMEM tiles (bf16 [row][128], 16B-chunk XOR swizzle): Qh Ql Kh Kl Vh Vl.
#define ATT_SMEM (6 * 32768)

__global__ __launch_bounds__(256, 1) void attn_kernel(float* __restrict__ comb)
{
    extern __shared__ char sm[];
    char* sQh = sm;
    char* sQl = sm + 32768;
    char* sKh = sm + 65536;
    char* sKl = sm + 98304;
    char* sVh = sm + 131072;
    char* sVl = sm + 163840;

    const int tid = threadIdx.x, lane = tid & 31, w = tid >> 5;
    const int qt = blockIdx.x, dir = blockIdx.y, b = blockIdx.z;
    const int qbase = qt * 128;
    const size_t PLANE = (size_t)DEMB * NPIX;

    const __nv_bfloat16* Qh = g_bf + ((size_t)(dir * 6 + 0) * NBATCH + b) * PLANE;
    const __nv_bfloat16* Ql = g_bf + ((size_t)(dir * 6 + 1) * NBATCH + b) * PLANE;
    const __nv_bfloat16* Kh = g_bf + ((size_t)(dir * 6 + 2) * NBATCH + b) * PLANE;
    const __nv_bfloat16* Kl = g_bf + ((size_t)(dir * 6 + 3) * NBATCH + b) * PLANE;
    const __nv_bfloat16* Vh = g_bf + ((size_t)(dir * 6 + 4) * NBATCH + b) * PLANE;
    const __nv_bfloat16* Vl = g_bf + ((size_t)(dir * 6 + 5) * NBATCH + b) * PLANE;
    float* Ob = comb + (size_t)b * 256 * NPIX + (size_t)dir * DEMB * NPIX;

    const uint32_t bQh = smem_u32(sQh), bQl = smem_u32(sQl);
    const uint32_t bKh = smem_u32(sKh), bKl = smem_u32(sKl);
    const uint32_t bVh = smem_u32(sVh), bVl = smem_u32(sVl);

    // tile fill: [row][16 chunks of 16B], chunk' = (c&8)|((c&7)^(r&7))
    auto fill = [&](char* dst, const __nv_bfloat16* src, int rstride) {
        for (int i = tid; i < 2048; i += 256) {
            int r = i >> 4, c = i & 15;
            uint4 v = *(const uint4*)(src + (size_t)r * rstride + c * 8);
            int ch = (c & 8) | ((c & 7) ^ (r & 7));
            *(uint4*)(dst + r * 256 + ch * 16) = v;
        }
    };

    // Q tiles (persist whole kernel)
    fill(sQh, Qh + (size_t)qbase * DEMB, DEMB);
    fill(sQl, Ql + (size_t)qbase * DEMB, DEMB);

    // ldmatrix lane geometry
    const int lr = lane & 7, g = lane >> 3;
    const int a_row = lr + ((g & 1) << 3), a_ch = g >> 1;   // A: m16k16
    const int b_row = lr + ((g >> 1) << 3), b_ch = g & 1;   // B: 2x n8k16
    const int q0 = 16 * w;

    float O[16][4];
#pragma unroll
    for (int i = 0; i < 16; i++)
#pragma unroll
        for (int j = 0; j < 4; j++) O[i][j] = 0.f;
    float l0 = 0.f, l1 = 0.f;

    for (int t = 0; t < 32; t++) {
        const int kbase = t * 128;
        fill(sKh, Kh + (size_t)kbase * DEMB, DEMB);
        fill(sKl, Kl + (size_t)kbase * DEMB, DEMB);
        fill(sVh, Vh + kbase, NPIX);
        fill(sVl, Vl + kbase, NPIX);
        __syncthreads();

        // ---- S = Q K^T (3-term split) ----
        float S[16][4];
#pragma unroll
        for (int i = 0; i < 16; i++)
#pragma unroll
            for (int j = 0; j < 4; j++) S[i][j] = 0.f;

#pragma unroll
        for (int k = 0; k < 8; k++) {
            uint32_t ah[4], al[4];
            {
                int ch = 2 * k + a_ch;
                uint32_t off = (q0 + a_row) * 256 + (((ch & 8) | ((ch & 7) ^ lr)) << 4);
                ldsm4(ah, bQh + off);
                ldsm4(al, bQl + off);
            }
#pragma unroll
            for (int nb = 0; nb < 8; nb++) {
                uint32_t bh[4], bl[4];
                {
                    int ch = 2 * k + b_ch;
                    uint32_t off = (nb * 16 + b_row) * 256 + (((ch & 8) | ((ch & 7) ^ lr)) << 4);
                    ldsm4(bh, bKh + off);
                    ldsm4(bl, bKl + off);
                }
                mma_bf16(S[2 * nb], ah, bh[0], bh[1]);
                mma_bf16(S[2 * nb], ah, bl[0], bl[1]);
                mma_bf16(S[2 * nb], al, bh[0], bh[1]);
                mma_bf16(S[2 * nb + 1], ah, bh[2], bh[3]);
                mma_bf16(S[2 * nb + 1], ah, bl[2], bl[3]);
                mma_bf16(S[2 * nb + 1], al, bh[2], bh[3]);
            }
        }

        // ---- softmax (no-max) + bf16 hi/lo A-fragments ----
        uint32_t ph[8][4], pl[8][4];
#pragma unroll
        for (int kk = 0; kk < 8; kk++) {
#pragma unroll
            for (int h = 0; h < 2; h++) {
                float* f = S[2 * kk + h];
                float e0 = __expf(f[0]), e1 = __expf(f[1]);
                float e2 = __expf(f[2]), e3 = __expf(f[3]);
                l0 += e0 + e1;
                l1 += e2 + e3;
                __nv_bfloat16 h0 = __float2bfloat16(e0), h1 = __float2bfloat16(e1);
                __nv_bfloat16 h2 = __float2bfloat16(e2), h3 = __float2bfloat16(e3);
                ph[kk][2 * h] = pk(h0, h1);
                ph[kk][2 * h + 1] = pk(h2, h3);
                pl[kk][2 * h] = pkf(e0 - __bfloat162float(h0), e1 - __bfloat162float(h1));
                pl[kk][2 * h + 1] = pkf(e2 - __bfloat162float(h2), e3 - __bfloat162float(h3));
            }
        }

        // ---- O += P V (3-term split) ----
#pragma unroll
        for (int k = 0; k < 8; k++) {
#pragma unroll
            for (int nb = 0; nb < 8; nb++) {
                uint32_t bh[4], bl[4];
                {
                    int ch = 2 * k + b_ch;
                    uint32_t off = (nb * 16 + b_row) * 256 + (((ch & 8) | ((ch & 7) ^ lr)) << 4);
                    ldsm4(bh, bVh + off);
                    ldsm4(bl, bVl + off);
                }
                mma_bf16(O[2 * nb], ph[k], bh[0], bh[1]);
                mma_bf16(O[2 * nb], ph[k], bl[0], bl[1]);
                mma_bf16(O[2 * nb], pl[k], bh[0], bh[1]);
                mma_bf16(O[2 * nb + 1], ph[k], bh[2], bh[3]);
                mma_bf16(O[2 * nb + 1], ph[k], bl[2], bl[3]);
                mma_bf16(O[2 * nb + 1], pl[k], bh[2], bh[3]);
            }
        }
        __syncthreads();
    }

    // row-sum reduce over the quad sharing each row
#pragma unroll
    for (int off = 1; off < 4; off <<= 1) {
        l0 += __shfl_xor_sync(0xffffffffu, l0, off);
        l1 += __shfl_xor_sync(0xffffffffu, l1, off);
    }
    const float inv0 = 1.f / l0, inv1 = 1.f / l1;

    const int qg0 = qbase + q0 + (lane >> 2);
#pragma unroll
    for (int nb = 0; nb < 16; nb++) {
        int d = nb * 8 + 2 * (lane & 3);
        Ob[(size_t)d * NPIX + qg0]           = O[nb][0] * inv0;
        Ob[(size_t)(d + 1) * NPIX + qg0]     = O[nb][1] * inv0;
        Ob[(size_t)d * NPIX + qg0 + 8]       = O[nb][2] * inv1;
        Ob[(size_t)(d + 1) * NPIX + qg0 + 8] = O[nb][3] * inv1;
    }
}

// ---------------- launch -----------------------------------------------------
extern "C" void kernel_launch(void* const* d_in, const int* in_sizes, int n_in,
                              void* d_out, int out_size)
{
    (void)in_sizes; (void)n_in; (void)out_size;
    const float* f_rgb   = (const float*)d_in[0];
    const float* f_pl    = (const float*)d_in[1];
    const float* w_q_rgb = (const float*)d_in[2];
    const float* b_q_rgb = (const float*)d_in[3];
    const float* w_k_pl  = (const float*)d_in[4];
    const float* b_k_pl  = (const float*)d_in[5];
    const float* w_v_pl  = (const float*)d_in[6];
    const float* b_v_pl  = (const float*)d_in[7];
    const float* w_q_pl  = (const float*)d_in[8];
    const float* b_q_pl  = (const float*)d_in[9];
    const float* w_k_rgb = (const float*)d_in[10];
    const float* b_k_rgb = (const float*)d_in[11];
    const float* w_v_rgb = (const float*)d_in[12];
    const float* b_v_rgb = (const float*)d_in[13];
    const float* w_proj  = (const float*)d_in[14];
    const float* bn_g    = (const float*)d_in[15];
    const float* bn_b    = (const float*)d_in[16];
    const float* bn_m    = (const float*)d_in[17];
    const float* bn_v    = (const float*)d_in[18];

    __nv_bfloat16* bfp = nullptr; float* combp = nullptr;
    cudaGetSymbolAddress((void**)&bfp, g_bf);
    cudaGetSymbolAddress((void**)&combp, g_comb);
    const size_t PL = (size_t)NBATCH * DEMB * NPIX;

    struct { const float* x; const float* w; const float* b; float s; int vm; int plane; } P[6] = {
        { f_rgb, w_q_rgb, b_q_rgb, ATT_SCALE, 0, 0 },
        { f_pl,  w_k_pl,  b_k_pl,  1.0f,      0, 2 },
        { f_pl,  w_v_pl,  b_v_pl,  1.0f,      1, 4 },
        { f_pl,  w_q_pl,  b_q_pl,  ATT_SCALE, 0, 6 },
        { f_rgb, w_k_rgb, b_k_rgb, 1.0f,      0, 8 },
        { f_rgb, w_v_rgb, b_v_rgb, 1.0f,      1, 10 },
    };

    dim3 blk(256), gp(32, 1, NBATCH);
    for (int p = 0; p < 6; p++)
        proj_kernel<<<gp, blk>>>(P[p].x, P[p].w, P[p].b,
                                 bfp + (size_t)P[p].plane * PL,
                                 bfp + (size_t)(P[p].plane + 1) * PL,
                                 P[p].s, P[p].vm);

    cudaFuncSetAttribute(attn_kernel, cudaFuncAttributeMaxDynamicSharedMemorySize, ATT_SMEM);
    attn_kernel<<<dim3(NPIX / 128, 2, NBATCH), 256, ATT_SMEM>>>(combp);

    final_kernel<<<dim3(32, 2, NBATCH), blk>>>(combp, w_proj, (float*)d_out,
                                               bn_g, bn_b, bn_m, bn_v);
}

// round 5
// speedup vs baseline: 4.8827x; 2.4750x over previous
#include <cuda_runtime.h>
#include <cuda_fp16.h>
#include <stdint.h>
#include <math.h>

#define NBATCH 8
#define NPIX   4096
#define DEMB   128
#define ATT_SCALE 0.08838834764831845f
#define BN_EPS 1e-5f

// fp16 planes: index (dir*3+kind), kind 0 Q,1 K,2 V.
// Q,K stored [n][d] (d contiguous, Q pre-scaled); V stored [d][n] (n contiguous).
__device__ __half g_h[(size_t)6 * NBATCH * DEMB * NPIX];   // 50 MB
__device__ float g_comb[(size_t)NBATCH * 256 * NPIX];      // 33.6 MB

// ------------------------------------------------------------- helpers -----
__device__ __forceinline__ uint32_t smem_u32(const void* p) {
    uint32_t a;
    asm("{ .reg .u64 t; cvta.to.shared.u64 t, %1; cvt.u32.u64 %0, t; }" : "=r"(a) : "l"(p));
    return a;
}
__device__ __forceinline__ uint32_t pkh(float a, float b) {
    __half2 h = __floats2half2_rn(a, b);
    return *reinterpret_cast<uint32_t*>(&h);
}
__device__ __forceinline__ void mma_f16(float c[4], const uint32_t a[4],
                                        uint32_t b0, uint32_t b1) {
    asm volatile("mma.sync.aligned.m16n8k16.row.col.f32.f16.f16.f32 "
        "{%0,%1,%2,%3}, {%4,%5,%6,%7}, {%8,%9}, {%0,%1,%2,%3};"
        : "+f"(c[0]), "+f"(c[1]), "+f"(c[2]), "+f"(c[3])
        : "r"(a[0]), "r"(a[1]), "r"(a[2]), "r"(a[3]), "r"(b0), "r"(b1));
}
__device__ __forceinline__ void ldsm4(uint32_t r[4], uint32_t addr) {
    asm volatile("ldmatrix.sync.aligned.m8n8.x4.shared.b16 {%0,%1,%2,%3}, [%4];"
        : "=r"(r[0]), "=r"(r[1]), "=r"(r[2]), "=r"(r[3]) : "r"(addr));
}
__device__ __forceinline__ void cpa16(uint32_t s, const void* g) {
    asm volatile("cp.async.cg.shared.global [%0], [%1], 16;" :: "r"(s), "l"(g));
}
#define CP_COMMIT() asm volatile("cp.async.commit_group;" ::: "memory")
#define CP_WAIT(n)  asm volatile("cp.async.wait_group %0;" :: "n"(n) : "memory")

// ---------------- merged projection GEMMs (6 in one launch) -----------------
struct ProjArgs {
    const float* x[6];
    const float* w[6];
    const float* b[6];
    __half* y[6];
    float scale[6];
    int vmode[6];
};

__global__ __launch_bounds__(256, 2) void proj_kernel(ProjArgs pa)
{
    __shared__ float Xs[32][128];
    __shared__ float Ws[32][132];
    const int tid = threadIdx.x;
    const int nbase = blockIdx.x * 128;
    const int p = blockIdx.y;
    const float* Xb = pa.x[p] + (size_t)blockIdx.z * 256 * NPIX;
    const float* W = pa.w[p];
    const float* bias = pa.b[p];
    __half* Yh = pa.y[p] + (size_t)blockIdx.z * DEMB * NPIX;
    const float scale = pa.scale[p];
    const int vmode = pa.vmode[p];

    float acc[8][8];
#pragma unroll
    for (int i = 0; i < 8; i++)
#pragma unroll
        for (int j = 0; j < 8; j++) acc[i][j] = 0.f;
    const int n0 = 8 * (tid % 16), m0 = 8 * (tid / 16);

    for (int k0 = 0; k0 < 256; k0 += 32) {
        {
            int r = tid / 32, c = 4 * (tid % 32);
#pragma unroll
            for (int q = 0; q < 4; q++)
                *(float4*)&Xs[r + 8 * q][c] =
                    *(const float4*)&Xb[(size_t)(k0 + r + 8 * q) * NPIX + nbase + c];
        }
        {
            int m = tid / 8, kk = 4 * (tid % 8);
#pragma unroll
            for (int q = 0; q < 4; q++) {
                int mm = m + 32 * q;
                float4 w = *(const float4*)&W[(size_t)mm * 256 + k0 + kk];
                Ws[kk + 0][mm] = w.x; Ws[kk + 1][mm] = w.y;
                Ws[kk + 2][mm] = w.z; Ws[kk + 3][mm] = w.w;
            }
        }
        __syncthreads();
#pragma unroll 4
        for (int kk = 0; kk < 32; kk++) {
            float4 xa = *(float4*)&Xs[kk][n0];
            float4 xb = *(float4*)&Xs[kk][n0 + 4];
            float4 wa = *(float4*)&Ws[kk][m0];
            float4 wb = *(float4*)&Ws[kk][m0 + 4];
            float xr[8] = {xa.x, xa.y, xa.z, xa.w, xb.x, xb.y, xb.z, xb.w};
            float wr[8] = {wa.x, wa.y, wa.z, wa.w, wb.x, wb.y, wb.z, wb.w};
#pragma unroll
            for (int i = 0; i < 8; i++)
#pragma unroll
                for (int j = 0; j < 8; j++) acc[i][j] = fmaf(wr[i], xr[j], acc[i][j]);
        }
        __syncthreads();
    }

    float bv[8];
#pragma unroll
    for (int i = 0; i < 8; i++) bv[i] = bias[m0 + i];

    if (vmode == 0) {  // [n][d], Q/K
#pragma unroll
        for (int j = 0; j < 8; j++) {
            size_t row = (size_t)(nbase + n0 + j) * DEMB;
#pragma unroll
            for (int i2 = 0; i2 < 4; i2++)
                ((uint32_t*)&Yh[row])[m0 / 2 + i2] =
                    pkh((acc[2 * i2][j] + bv[2 * i2]) * scale,
                        (acc[2 * i2 + 1][j] + bv[2 * i2 + 1]) * scale);
        }
    } else {  // [d][n], V
#pragma unroll
        for (int i = 0; i < 8; i++) {
            size_t row = (size_t)(m0 + i) * NPIX;
#pragma unroll
            for (int j2 = 0; j2 < 4; j2++)
                ((uint32_t*)&Yh[row])[(nbase + n0) / 2 + j2] =
                    pkh(acc[i][2 * j2] + bv[i], acc[i][2 * j2 + 1] + bv[i]);
        }
    }
}

// ---------------- final GEMM: out = relu(BN(W(256,256)@comb)) ---------------
__global__ __launch_bounds__(256, 2) void final_kernel(
    const float* __restrict__ X, const float* __restrict__ W, float* __restrict__ Y,
    const float* __restrict__ bng, const float* __restrict__ bnb,
    const float* __restrict__ bnm, const float* __restrict__ bnv)
{
    __shared__ float Xs[32][128];
    __shared__ float Ws[32][132];
    const int tid = threadIdx.x;
    const int nbase = blockIdx.x * 128;
    const int mbase = blockIdx.y * 128;
    const float* Xb = X + (size_t)blockIdx.z * 256 * NPIX;
    float* Yb = Y + (size_t)blockIdx.z * 256 * NPIX;

    float acc[8][8];
#pragma unroll
    for (int i = 0; i < 8; i++)
#pragma unroll
        for (int j = 0; j < 8; j++) acc[i][j] = 0.f;
    const int n0 = 8 * (tid % 16), m0 = 8 * (tid / 16);

    for (int k0 = 0; k0 < 256; k0 += 32) {
        {
            int r = tid / 32, c = 4 * (tid % 32);
#pragma unroll
            for (int q = 0; q < 4; q++)
                *(float4*)&Xs[r + 8 * q][c] =
                    *(const float4*)&Xb[(size_t)(k0 + r + 8 * q) * NPIX + nbase + c];
        }
        {
            int m = tid / 8, kk = 4 * (tid % 8);
#pragma unroll
            for (int q = 0; q < 4; q++) {
                int mm = m + 32 * q;
                float4 w = *(const float4*)&W[(size_t)(mbase + mm) * 256 + k0 + kk];
                Ws[kk + 0][mm] = w.x; Ws[kk + 1][mm] = w.y;
                Ws[kk + 2][mm] = w.z; Ws[kk + 3][mm] = w.w;
            }
        }
        __syncthreads();
#pragma unroll 4
        for (int kk = 0; kk < 32; kk++) {
            float4 xa = *(float4*)&Xs[kk][n0];
            float4 xb = *(float4*)&Xs[kk][n0 + 4];
            float4 wa = *(float4*)&Ws[kk][m0];
            float4 wb = *(float4*)&Ws[kk][m0 + 4];
            float xr[8] = {xa.x, xa.y, xa.z, xa.w, xb.x, xb.y, xb.z, xb.w};
            float wr[8] = {wa.x, wa.y, wa.z, wa.w, wb.x, wb.y, wb.z, wb.w};
#pragma unroll
            for (int i = 0; i < 8; i++)
#pragma unroll
                for (int j = 0; j < 8; j++) acc[i][j] = fmaf(wr[i], xr[j], acc[i][j]);
        }
        __syncthreads();
    }
#pragma unroll
    for (int i = 0; i < 8; i++) {
        int m = mbase + m0 + i;
        float inv = bng[m] * rsqrtf(bnv[m] + BN_EPS);
        float sh = bnb[m] - bnm[m] * inv;
        float o[8];
#pragma unroll
        for (int j = 0; j < 8; j++) o[j] = fmaxf(fmaf(acc[i][j], inv, sh), 0.f);
        float* dst = &Yb[(size_t)m * NPIX + nbase + n0];
        *(float4*)dst = make_float4(o[0], o[1], o[2], o[3]);
        *(float4*)(dst + 4) = make_float4(o[4], o[5], o[6], o[7]);
    }
}

// ---------------- warp-MMA flash attention (fp16, double-buffered) ----------
// smem: Q 32KB | K buf0/1 32KB each | V buf0/1 32KB each = 160KB
#define ATT_SMEM (5 * 32768)

__global__ __launch_bounds__(256, 1) void attn_kernel(float* __restrict__ comb)
{
    extern __shared__ char sm[];
    const int tid = threadIdx.x, lane = tid & 31, w = tid >> 5;
    const int qt = blockIdx.x, dir = blockIdx.y, b = blockIdx.z;
    const int qbase = qt * 128;
    const size_t PLANE = (size_t)DEMB * NPIX;

    const __half* Qg = g_h + ((size_t)(dir * 3 + 0) * NBATCH + b) * PLANE;
    const __half* Kg = g_h + ((size_t)(dir * 3 + 1) * NBATCH + b) * PLANE;
    const __half* Vg = g_h + ((size_t)(dir * 3 + 2) * NBATCH + b) * PLANE;
    float* Ob = comb + (size_t)b * 256 * NPIX + (size_t)dir * DEMB * NPIX;

    const uint32_t bQ = smem_u32(sm);
    const uint32_t bK0 = bQ + 32768, bK1 = bQ + 65536;
    const uint32_t bV0 = bQ + 98304, bV1 = bQ + 131072;

    // async fill of one 128x128 fp16 tile, 16B-chunk XOR swizzle
    auto fillA = [&](uint32_t dst, const __half* src, int rstride) {
#pragma unroll
        for (int i = 0; i < 8; i++) {
            int idx = tid + 256 * i;
            int r = idx >> 4, c = idx & 15;
            int ch = (c & 8) | ((c & 7) ^ (r & 7));
            cpa16(dst + r * 256 + ch * 16, src + (size_t)r * rstride + c * 8);
        }
    };

    fillA(bQ, Qg + (size_t)qbase * DEMB, DEMB);           CP_COMMIT();  // group Q
    fillA(bK0, Kg, DEMB); fillA(bV0, Vg, NPIX);           CP_COMMIT();  // tile 0
    fillA(bK1, Kg + (size_t)128 * DEMB, DEMB);
    fillA(bV1, Vg + 128, NPIX);                           CP_COMMIT();  // tile 1

    // lane geometry
    const int lr = lane & 7, g = lane >> 3;
    const int a_row = lr + ((g & 1) << 3), a_ch = g >> 1;
    const int b_row = lr + ((g >> 1) << 3), b_ch = g & 1;
    const int q0 = 16 * w;

    CP_WAIT(2);
    __syncthreads();

    // preload Q fragments (persist in registers)
    uint32_t qf[8][4];
#pragma unroll
    for (int k = 0; k < 8; k++) {
        int ch = 2 * k + a_ch;
        ldsm4(qf[k], bQ + (q0 + a_row) * 256 + (((ch & 8) | ((ch & 7) ^ lr)) << 4));
    }

    float O[16][4];
#pragma unroll
    for (int i = 0; i < 16; i++)
#pragma unroll
        for (int j = 0; j < 4; j++) O[i][j] = 0.f;
    float l0 = 0.f, l1 = 0.f;

    for (int t = 0; t < 32; t++) {
        if (t < 30) { CP_WAIT(1); } else { CP_WAIT(0); }
        __syncthreads();
        const uint32_t bK = (t & 1) ? bK1 : bK0;
        const uint32_t bV = (t & 1) ? bV1 : bV0;

#pragma unroll 2
        for (int kc = 0; kc < 8; kc++) {   // 16-key chunk
            // S(16x16) = Q . K[kc]^T
            float S0[4] = {0.f, 0.f, 0.f, 0.f}, S1[4] = {0.f, 0.f, 0.f, 0.f};
#pragma unroll
            for (int d = 0; d < 8; d++) {
                uint32_t bk[4];
                int ch = 2 * d + b_ch;
                ldsm4(bk, bK + (kc * 16 + b_row) * 256 + (((ch & 8) | ((ch & 7) ^ lr)) << 4));
                mma_f16(S0, qf[d], bk[0], bk[1]);
                mma_f16(S1, qf[d], bk[2], bk[3]);
            }
            // exp -> P fragment (no-max softmax)
            float e00 = __expf(S0[0]), e01 = __expf(S0[1]);
            float e02 = __expf(S0[2]), e03 = __expf(S0[3]);
            float e10 = __expf(S1[0]), e11 = __expf(S1[1]);
            float e12 = __expf(S1[2]), e13 = __expf(S1[3]);
            l0 += e00 + e01 + e10 + e11;
            l1 += e02 + e03 + e12 + e13;
            uint32_t ph[4];
            ph[0] = pkh(e00, e01); ph[1] = pkh(e02, e03);
            ph[2] = pkh(e10, e11); ph[3] = pkh(e12, e13);
            // O += P[.,kc] V[kc,.]
#pragma unroll
            for (int nb = 0; nb < 8; nb++) {
                uint32_t bv[4];
                int ch = 2 * kc + b_ch;
                ldsm4(bv, bV + (nb * 16 + b_row) * 256 + (((ch & 8) | ((ch & 7) ^ lr)) << 4));
                mma_f16(O[2 * nb], ph, bv[0], bv[1]);
                mma_f16(O[2 * nb + 1], ph, bv[2], bv[3]);
            }
        }
        __syncthreads();
        if (t + 2 < 32) {
            const uint32_t dK = (t & 1) ? bK1 : bK0;
            const uint32_t dV = (t & 1) ? bV1 : bV0;
            fillA(dK, Kg + (size_t)(t + 2) * 128 * DEMB, DEMB);
            fillA(dV, Vg + (t + 2) * 128, NPIX);
            CP_COMMIT();
        }
    }

#pragma unroll
    for (int off = 1; off < 4; off <<= 1) {
        l0 += __shfl_xor_sync(0xffffffffu, l0, off);
        l1 += __shfl_xor_sync(0xffffffffu, l1, off);
    }
    const float inv0 = 1.f / l0, inv1 = 1.f / l1;

    const int qg0 = qbase + q0 + (lane >> 2);
#pragma unroll
    for (int nb = 0; nb < 16; nb++) {
        int d = nb * 8 + 2 * (lane & 3);
        Ob[(size_t)d * NPIX + qg0]           = O[nb][0] * inv0;
        Ob[(size_t)(d + 1) * NPIX + qg0]     = O[nb][1] * inv0;
        Ob[(size_t)d * NPIX + qg0 + 8]       = O[nb][2] * inv1;
        Ob[(size_t)(d + 1) * NPIX + qg0 + 8] = O[nb][3] * inv1;
    }
}

// ---------------- launch -----------------------------------------------------
extern "C" void kernel_launch(void* const* d_in, const int* in_sizes, int n_in,
                              void* d_out, int out_size)
{
    (void)in_sizes; (void)n_in; (void)out_size;
    const float* f_rgb   = (const float*)d_in[0];
    const float* f_pl    = (const float*)d_in[1];
    const float* w_q_rgb = (const float*)d_in[2];
    const float* b_q_rgb = (const float*)d_in[3];
    const float* w_k_pl  = (const float*)d_in[4];
    const float* b_k_pl  = (const float*)d_in[5];
    const float* w_v_pl  = (const float*)d_in[6];
    const float* b_v_pl  = (const float*)d_in[7];
    const float* w_q_pl  = (const float*)d_in[8];
    const float* b_q_pl  = (const float*)d_in[9];
    const float* w_k_rgb = (const float*)d_in[10];
    const float* b_k_rgb = (const float*)d_in[11];
    const float* w_v_rgb = (const float*)d_in[12];
    const float* b_v_rgb = (const float*)d_in[13];
    const float* w_proj  = (const float*)d_in[14];
    const float* bn_g    = (const float*)d_in[15];
    const float* bn_b    = (const float*)d_in[16];
    const float* bn_m    = (const float*)d_in[17];
    const float* bn_v    = (const float*)d_in[18];

    __half* hp = nullptr; float* combp = nullptr;
    cudaGetSymbolAddress((void**)&hp, g_h);
    cudaGetSymbolAddress((void**)&combp, g_comb);
    const size_t PL = (size_t)NBATCH * DEMB * NPIX;

    ProjArgs pa;
    const float* xs[6] = { f_rgb, f_pl, f_pl, f_pl, f_rgb, f_rgb };
    const float* ws[6] = { w_q_rgb, w_k_pl, w_v_pl, w_q_pl, w_k_rgb, w_v_rgb };
    const float* bs[6] = { b_q_rgb, b_k_pl, b_v_pl, b_q_pl, b_k_rgb, b_v_rgb };
    const float sc[6]  = { ATT_SCALE, 1.f, 1.f, ATT_SCALE, 1.f, 1.f };
    const int vm[6]    = { 0, 0, 1, 0, 0, 1 };
    for (int p = 0; p < 6; p++) {
        pa.x[p] = xs[p]; pa.w[p] = ws[p]; pa.b[p] = bs[p];
        pa.y[p] = hp + (size_t)p * PL;
        pa.scale[p] = sc[p]; pa.vmode[p] = vm[p];
    }

    proj_kernel<<<dim3(32, 6, NBATCH), 256>>>(pa);

    cudaFuncSetAttribute(attn_kernel, cudaFuncAttributeMaxDynamicSharedMemorySize, ATT_SMEM);
    attn_kernel<<<dim3(NPIX / 128, 2, NBATCH), 256, ATT_SMEM>>>(combp);

    final_kernel<<<dim3(32, 2, NBATCH), 256>>>(combp, w_proj, (float*)d_out,
                                               bn_g, bn_b, bn_m, bn_v);
}

// round 6
// speedup vs baseline: 6.3287x; 1.2961x over previous
#include <cuda_runtime.h>
#include <cuda_fp16.h>
#include <stdint.h>
#include <math.h>

#define NBATCH 8
#define NPIX   4096
#define DEMB   128
#define ATT_SCALE 0.08838834764831845f
#define BN_EPS 1e-5f

// fp16 single planes for attention operands: (dir*3+kind), kind 0 Q,1 K,2 V.
// Q,K stored [n][d]; V stored [d][n].
__device__ __half g_h[(size_t)6 * NBATCH * DEMB * NPIX];        // 50 MB
// input features converted to hi/lo fp16, layout [input][b][k=256][n=4096]
__device__ __half g_xh[(size_t)2 * NBATCH * 256 * NPIX];        // 33.5 MB
__device__ __half g_xl[(size_t)2 * NBATCH * 256 * NPIX];
// attention output (concat) hi/lo planes [b][256][4096]
__device__ __half g_ch[(size_t)NBATCH * 256 * NPIX];            // 16.8 MB
__device__ __half g_cl[(size_t)NBATCH * 256 * NPIX];
// weights hi/lo: 6 proj W [128][256] at p*32768, then w_proj [256][256] at 196608
__device__ __half g_wh[262144];
__device__ __half g_wl[262144];

// ------------------------------------------------------------- helpers -----
__device__ __forceinline__ uint32_t smem_u32(const void* p) {
    uint32_t a;
    asm("{ .reg .u64 t; cvta.to.shared.u64 t, %1; cvt.u32.u64 %0, t; }" : "=r"(a) : "l"(p));
    return a;
}
__device__ __forceinline__ uint32_t pkh(float a, float b) {
    __half2 h = __floats2half2_rn(a, b);
    return *reinterpret_cast<uint32_t*>(&h);
}
__device__ __forceinline__ void mma_f16(float c[4], const uint32_t a[4],
                                        uint32_t b0, uint32_t b1) {
    asm volatile("mma.sync.aligned.m16n8k16.row.col.f32.f16.f16.f32 "
        "{%0,%1,%2,%3}, {%4,%5,%6,%7}, {%8,%9}, {%0,%1,%2,%3};"
        : "+f"(c[0]), "+f"(c[1]), "+f"(c[2]), "+f"(c[3])
        : "r"(a[0]), "r"(a[1]), "r"(a[2]), "r"(a[3]), "r"(b0), "r"(b1));
}
__device__ __forceinline__ void ldsm4(uint32_t r[4], uint32_t addr) {
    asm volatile("ldmatrix.sync.aligned.m8n8.x4.shared.b16 {%0,%1,%2,%3}, [%4];"
        : "=r"(r[0]), "=r"(r[1]), "=r"(r[2]), "=r"(r[3]) : "r"(addr));
}
__device__ __forceinline__ void ldsm4t(uint32_t r[4], uint32_t addr) {
    asm volatile("ldmatrix.sync.aligned.m8n8.x4.trans.shared.b16 {%0,%1,%2,%3}, [%4];"
        : "=r"(r[0]), "=r"(r[1]), "=r"(r[2]), "=r"(r[3]) : "r"(addr));
}
__device__ __forceinline__ void cpa16(uint32_t s, const void* g) {
    asm volatile("cp.async.cg.shared.global [%0], [%1], 16;" :: "r"(s), "l"(g));
}
#define CP_COMMIT() asm volatile("cp.async.commit_group;" ::: "memory")
#define CP_WAIT(n)  asm volatile("cp.async.wait_group %0;" :: "n"(n) : "memory")

// ---------------- fp32 -> fp16 hi/lo converter ------------------------------
__global__ void cvt_kernel(const float* __restrict__ src,
                           __half* __restrict__ dh, __half* __restrict__ dl, int n)
{
    int i = (blockIdx.x * 256 + threadIdx.x) * 8;
    if (i >= n) return;
    float4 a = *(const float4*)(src + i);
    float4 b = *(const float4*)(src + i + 4);
    float v[8] = {a.x, a.y, a.z, a.w, b.x, b.y, b.z, b.w};
    uint32_t h[4], l[4];
#pragma unroll
    for (int j = 0; j < 4; j++) {
        __half h0 = __float2half_rn(v[2 * j]), h1 = __float2half_rn(v[2 * j + 1]);
        h[j] = pkh(__half2float(h0), __half2float(h1));   // exact repack
        __half2 hh(h0, h1);
        h[j] = *reinterpret_cast<uint32_t*>(&hh);
        l[j] = pkh(v[2 * j] - __half2float(h0), v[2 * j + 1] - __half2float(h1));
    }
    *(uint2*)(dh + i)     = make_uint2(h[0], h[1]);
    *(uint2*)(dh + i + 4) = make_uint2(h[2], h[3]);
    *(uint2*)(dl + i)     = make_uint2(l[0], l[1]);
    *(uint2*)(dl + i + 4) = make_uint2(l[2], l[3]);
}

// ---------------- tensor GEMM skeleton shared constants ---------------------
// smem per buffer: X [64][272B] = 17408, W [128][144B] = 18432 per plane
#define SB_XH 0
#define SB_XL 17408
#define SB_WH 34816
#define SB_WL 53248
#define SB_BUF 71680
#define GEMM_SMEM (2 * SB_BUF)

struct ProjTab {
    int woff[6];            // halves offset into g_wh/g_wl
    const float* bias[6];
    float scale[6];
    int vmode[6];           // 0: out [n][d], 1: out [d][n]
    __half* out[6];         // plane base (batch added in kernel)
};

// proj: Y(128, 4096-tile) = W(128,256) @ X(256,4096) + bias, out fp16 planes
__global__ __launch_bounds__(256) void proj_mma(ProjTab pt)
{
    extern __shared__ char sm[];
    const int tid = threadIdx.x, lane = tid & 31, w = tid >> 5;
    const int nb = blockIdx.x * 128;
    const int input = blockIdx.z >> 3, b = blockIdx.z & 7;
    const int p = input * 3 + blockIdx.y;

    const __half* Xh = g_xh + (size_t)(input * 8 + b) * 256 * NPIX;
    const __half* Xl = g_xl + (size_t)(input * 8 + b) * 256 * NPIX;
    const __half* Wh = g_wh + pt.woff[p];
    const __half* Wl = g_wl + pt.woff[p];
    const float* bias = pt.bias[p];
    const float scale = pt.scale[p];
    const int vmode = pt.vmode[p];
    __half* out = pt.out[p] + (size_t)b * DEMB * NPIX;

    const uint32_t sb = smem_u32(sm);

    auto fill = [&](int c, int s) {
        uint32_t base = sb + s * SB_BUF;
#pragma unroll
        for (int i = 0; i < 4; i++) {   // X: 64 rows x 16 chunks
            int idx = tid + 256 * i, r = idx >> 4, ch = idx & 15;
            const size_t go = (size_t)(c * 64 + r) * NPIX + nb + ch * 8;
            cpa16(base + SB_XH + r * 272 + ch * 16, Xh + go);
            cpa16(base + SB_XL + r * 272 + ch * 16, Xl + go);
        }
#pragma unroll
        for (int i = 0; i < 4; i++) {   // W: 128 rows x 8 chunks
            int idx = tid + 256 * i, m = idx >> 3, ch = idx & 7;
            const size_t go = (size_t)m * 256 + c * 64 + ch * 8;
            cpa16(base + SB_WH + m * 144 + ch * 16, Wh + go);
            cpa16(base + SB_WL + m * 144 + ch * 16, Wl + go);
        }
    };

    fill(0, 0); CP_COMMIT();
    fill(1, 1); CP_COMMIT();

    const int lr = lane & 7, g = lane >> 3;
    const int fr = lr + ((g & 1) << 3), fc = g >> 1;
    const int wm = w >> 2, wn = w & 3;

    float C[4][4][4];
#pragma unroll
    for (int i = 0; i < 4; i++)
#pragma unroll
        for (int j = 0; j < 4; j++)
#pragma unroll
            for (int k = 0; k < 4; k++) C[i][j][k] = 0.f;

    for (int c = 0; c < 4; c++) {
        if (c < 2) { CP_WAIT(1); } else { CP_WAIT(0); }
        __syncthreads();
        const uint32_t base = sb + (c & 1) * SB_BUF;
#pragma unroll
        for (int kt = 0; kt < 4; kt++) {
            uint32_t ah[4][4], al[4][4];
#pragma unroll
            for (int mt = 0; mt < 4; mt++) {
                uint32_t ad = base + (wm * 64 + mt * 16 + fr) * 144 + (kt * 16 + fc * 8) * 2;
                ldsm4(ah[mt], ad + SB_WH);
                ldsm4(al[mt], ad + SB_WL);
            }
            uint32_t bh[2][4], bl[2][4];
#pragma unroll
            for (int nh = 0; nh < 2; nh++) {
                uint32_t ad = base + (kt * 16 + fr) * 272 + (wn * 32 + nh * 16 + fc * 8) * 2;
                ldsm4t(bh[nh], ad + SB_XH);
                ldsm4t(bl[nh], ad + SB_XL);
            }
#pragma unroll
            for (int mt = 0; mt < 4; mt++)
#pragma unroll
                for (int nh = 0; nh < 2; nh++) {
                    mma_f16(C[mt][2 * nh], ah[mt], bh[nh][0], bh[nh][1]);
                    mma_f16(C[mt][2 * nh], ah[mt], bl[nh][0], bl[nh][1]);
                    mma_f16(C[mt][2 * nh], al[mt], bh[nh][0], bh[nh][1]);
                    mma_f16(C[mt][2 * nh + 1], ah[mt], bh[nh][2], bh[nh][3]);
                    mma_f16(C[mt][2 * nh + 1], ah[mt], bl[nh][2], bl[nh][3]);
                    mma_f16(C[mt][2 * nh + 1], al[mt], bh[nh][2], bh[nh][3]);
                }
        }
        __syncthreads();
        if (c + 2 < 4) { fill(c + 2, c & 1); CP_COMMIT(); }
    }

    // epilogue: bias+scale, fp16, stage to target layout in smem buf0
    __half* stage = (__half*)sm;    // rows pitch 272B = 136 halves
#pragma unroll
    for (int mt = 0; mt < 4; mt++) {
        int m0 = wm * 64 + mt * 16 + (lane >> 2);
        float b0 = bias[m0], b1 = bias[m0 + 8];
#pragma unroll
        for (int nt = 0; nt < 4; nt++) {
            int n = wn * 32 + nt * 8 + 2 * (lane & 3);
            float v0 = (C[mt][nt][0] + b0) * scale;
            float v1 = (C[mt][nt][1] + b0) * scale;
            float v2 = (C[mt][nt][2] + b1) * scale;
            float v3 = (C[mt][nt][3] + b1) * scale;
            if (vmode == 0) {   // stage [n][d]
                stage[n * 136 + m0] = __float2half_rn(v0);
                stage[(n + 1) * 136 + m0] = __float2half_rn(v1);
                stage[n * 136 + m0 + 8] = __float2half_rn(v2);
                stage[(n + 1) * 136 + m0 + 8] = __float2half_rn(v3);
            } else {            // stage [d][n]
                *(uint32_t*)&stage[m0 * 136 + n] = pkh(v0, v1);
                *(uint32_t*)&stage[(m0 + 8) * 136 + n] = pkh(v2, v3);
            }
        }
    }
    __syncthreads();
#pragma unroll
    for (int i = 0; i < 8; i++) {
        int idx = tid + 256 * i, r = idx >> 4, ch = idx & 15;
        uint4 v = *(uint4*)((char*)sm + r * 272 + ch * 16);
        if (vmode == 0)
            *(uint4*)(out + (size_t)(nb + r) * DEMB + ch * 8) = v;
        else
            *(uint4*)(out + (size_t)r * NPIX + nb + ch * 8) = v;
    }
}

// final: out(256,4096) = BN(ReLU(Wp(256,256) @ comb)) fp32
__global__ __launch_bounds__(256) void final_mma(
    float* __restrict__ Y,
    const float* __restrict__ bng, const float* __restrict__ bnb,
    const float* __restrict__ bnm, const float* __restrict__ bnv)
{
    extern __shared__ char sm[];
    const int tid = threadIdx.x, lane = tid & 31, w = tid >> 5;
    const int nb = blockIdx.x * 128;
    const int mbase = blockIdx.y * 128;
    const int b = blockIdx.z;

    const __half* Xh = g_ch + (size_t)b * 256 * NPIX;
    const __half* Xl = g_cl + (size_t)b * 256 * NPIX;
    const __half* Wh = g_wh + 196608;
    const __half* Wl = g_wl + 196608;
    float* Yb = Y + (size_t)b * 256 * NPIX;

    const uint32_t sb = smem_u32(sm);

    auto fill = [&](int c, int s) {
        uint32_t base = sb + s * SB_BUF;
#pragma unroll
        for (int i = 0; i < 4; i++) {
            int idx = tid + 256 * i, r = idx >> 4, ch = idx & 15;
            const size_t go = (size_t)(c * 64 + r) * NPIX + nb + ch * 8;
            cpa16(base + SB_XH + r * 272 + ch * 16, Xh + go);
            cpa16(base + SB_XL + r * 272 + ch * 16, Xl + go);
        }
#pragma unroll
        for (int i = 0; i < 4; i++) {
            int idx = tid + 256 * i, m = idx >> 3, ch = idx & 7;
            const size_t go = (size_t)(mbase + m) * 256 + c * 64 + ch * 8;
            cpa16(base + SB_WH + m * 144 + ch * 16, Wh + go);
            cpa16(base + SB_WL + m * 144 + ch * 16, Wl + go);
        }
    };

    fill(0, 0); CP_COMMIT();
    fill(1, 1); CP_COMMIT();

    const int lr = lane & 7, g = lane >> 3;
    const int fr = lr + ((g & 1) << 3), fc = g >> 1;
    const int wm = w >> 2, wn = w & 3;

    float C[4][4][4];
#pragma unroll
    for (int i = 0; i < 4; i++)
#pragma unroll
        for (int j = 0; j < 4; j++)
#pragma unroll
            for (int k = 0; k < 4; k++) C[i][j][k] = 0.f;

    for (int c = 0; c < 4; c++) {
        if (c < 2) { CP_WAIT(1); } else { CP_WAIT(0); }
        __syncthreads();
        const uint32_t base = sb + (c & 1) * SB_BUF;
#pragma unroll
        for (int kt = 0; kt < 4; kt++) {
            uint32_t ah[4][4], al[4][4];
#pragma unroll
            for (int mt = 0; mt < 4; mt++) {
                uint32_t ad = base + (wm * 64 + mt * 16 + fr) * 144 + (kt * 16 + fc * 8) * 2;
                ldsm4(ah[mt], ad + SB_WH);
                ldsm4(al[mt], ad + SB_WL);
            }
            uint32_t bh[2][4], bl[2][4];
#pragma unroll
            for (int nh = 0; nh < 2; nh++) {
                uint32_t ad = base + (kt * 16 + fr) * 272 + (wn * 32 + nh * 16 + fc * 8) * 2;
                ldsm4t(bh[nh], ad + SB_XH);
                ldsm4t(bl[nh], ad + SB_XL);
            }
#pragma unroll
            for (int mt = 0; mt < 4; mt++)
#pragma unroll
                for (int nh = 0; nh < 2; nh++) {
                    mma_f16(C[mt][2 * nh], ah[mt], bh[nh][0], bh[nh][1]);
                    mma_f16(C[mt][2 * nh], ah[mt], bl[nh][0], bl[nh][1]);
                    mma_f16(C[mt][2 * nh], al[mt], bh[nh][0], bh[nh][1]);
                    mma_f16(C[mt][2 * nh + 1], ah[mt], bh[nh][2], bh[nh][3]);
                    mma_f16(C[mt][2 * nh + 1], ah[mt], bl[nh][2], bl[nh][3]);
                    mma_f16(C[mt][2 * nh + 1], al[mt], bh[nh][2], bh[nh][3]);
                }
        }
        __syncthreads();
        if (c + 2 < 4) { fill(c + 2, c & 1); CP_COMMIT(); }
    }

    // BN + ReLU, stage fp32 [m][n] pitch 132 floats, then coalesced STG
    float* stage = (float*)sm;
#pragma unroll
    for (int mt = 0; mt < 4; mt++) {
        int ml = wm * 64 + mt * 16 + (lane >> 2);
        int m0 = mbase + ml, m1 = m0 + 8;
        float i0 = bng[m0] * rsqrtf(bnv[m0] + BN_EPS);
        float s0 = bnb[m0] - bnm[m0] * i0;
        float i1 = bng[m1] * rsqrtf(bnv[m1] + BN_EPS);
        float s1 = bnb[m1] - bnm[m1] * i1;
#pragma unroll
        for (int nt = 0; nt < 4; nt++) {
            int n = wn * 32 + nt * 8 + 2 * (lane & 3);
            stage[ml * 132 + n]       = fmaxf(fmaf(C[mt][nt][0], i0, s0), 0.f);
            stage[ml * 132 + n + 1]   = fmaxf(fmaf(C[mt][nt][1], i0, s0), 0.f);
            stage[(ml + 8) * 132 + n]     = fmaxf(fmaf(C[mt][nt][2], i1, s1), 0.f);
            stage[(ml + 8) * 132 + n + 1] = fmaxf(fmaf(C[mt][nt][3], i1, s1), 0.f);
        }
    }
    __syncthreads();
#pragma unroll
    for (int i = 0; i < 16; i++) {
        int idx = tid + 256 * i, r = idx >> 5, ch = idx & 31;
        float4 v = *(float4*)((char*)sm + r * 528 + ch * 16);
        *(float4*)&Yb[(size_t)(mbase + r) * NPIX + nb + ch * 4] = v;
    }
}

// ---------------- warp-MMA flash attention (fp16, double-buffered) ----------
#define ATT_SMEM (5 * 32768)

__global__ __launch_bounds__(256, 1) void attn_kernel()
{
    extern __shared__ char sm[];
    const int tid = threadIdx.x, lane = tid & 31, w = tid >> 5;
    const int qt = blockIdx.x, dir = blockIdx.y, b = blockIdx.z;
    const int qbase = qt * 128;
    const size_t PLANE = (size_t)DEMB * NPIX;

    const __half* Qg = g_h + ((size_t)(dir * 3 + 0) * NBATCH + b) * PLANE;
    const __half* Kg = g_h + ((size_t)(dir * 3 + 1) * NBATCH + b) * PLANE;
    const __half* Vg = g_h + ((size_t)(dir * 3 + 2) * NBATCH + b) * PLANE;
    __half* Oh = g_ch + ((size_t)b * 256 + dir * 128) * NPIX;
    __half* Ol = g_cl + ((size_t)b * 256 + dir * 128) * NPIX;

    const uint32_t bQ = smem_u32(sm);
    const uint32_t bK0 = bQ + 32768, bK1 = bQ + 65536;
    const uint32_t bV0 = bQ + 98304, bV1 = bQ + 131072;

    auto fillA = [&](uint32_t dst, const __half* src, int rstride) {
#pragma unroll
        for (int i = 0; i < 8; i++) {
            int idx = tid + 256 * i;
            int r = idx >> 4, c = idx & 15;
            int ch = (c & 8) | ((c & 7) ^ (r & 7));
            cpa16(dst + r * 256 + ch * 16, src + (size_t)r * rstride + c * 8);
        }
    };

    fillA(bQ, Qg + (size_t)qbase * DEMB, DEMB);           CP_COMMIT();
    fillA(bK0, Kg, DEMB); fillA(bV0, Vg, NPIX);           CP_COMMIT();
    fillA(bK1, Kg + (size_t)128 * DEMB, DEMB);
    fillA(bV1, Vg + 128, NPIX);                           CP_COMMIT();

    const int lr = lane & 7, g = lane >> 3;
    const int a_row = lr + ((g & 1) << 3), a_ch = g >> 1;
    const int b_row = lr + ((g >> 1) << 3), b_ch = g & 1;
    const int q0 = 16 * w;

    CP_WAIT(2);
    __syncthreads();

    uint32_t qf[8][4];
#pragma unroll
    for (int k = 0; k < 8; k++) {
        int ch = 2 * k + a_ch;
        ldsm4(qf[k], bQ + (q0 + a_row) * 256 + (((ch & 8) | ((ch & 7) ^ lr)) << 4));
    }

    float O[16][4];
#pragma unroll
    for (int i = 0; i < 16; i++)
#pragma unroll
        for (int j = 0; j < 4; j++) O[i][j] = 0.f;
    float l0 = 0.f, l1 = 0.f;

    for (int t = 0; t < 32; t++) {
        if (t < 30) { CP_WAIT(1); } else { CP_WAIT(0); }
        __syncthreads();
        const uint32_t bK = (t & 1) ? bK1 : bK0;
        const uint32_t bV = (t & 1) ? bV1 : bV0;

#pragma unroll 2
        for (int kc = 0; kc < 8; kc++) {
            float S0[4] = {0.f, 0.f, 0.f, 0.f}, S1[4] = {0.f, 0.f, 0.f, 0.f};
#pragma unroll
            for (int d = 0; d < 8; d++) {
                uint32_t bk[4];
                int ch = 2 * d + b_ch;
                ldsm4(bk, bK + (kc * 16 + b_row) * 256 + (((ch & 8) | ((ch & 7) ^ lr)) << 4));
                mma_f16(S0, qf[d], bk[0], bk[1]);
                mma_f16(S1, qf[d], bk[2], bk[3]);
            }
            float e00 = __expf(S0[0]), e01 = __expf(S0[1]);
            float e02 = __expf(S0[2]), e03 = __expf(S0[3]);
            float e10 = __expf(S1[0]), e11 = __expf(S1[1]);
            float e12 = __expf(S1[2]), e13 = __expf(S1[3]);
            l0 += e00 + e01 + e10 + e11;
            l1 += e02 + e03 + e12 + e13;
            uint32_t ph[4];
            ph[0] = pkh(e00, e01); ph[1] = pkh(e02, e03);
            ph[2] = pkh(e10, e11); ph[3] = pkh(e12, e13);
#pragma unroll
            for (int nb2 = 0; nb2 < 8; nb2++) {
                uint32_t bv[4];
                int ch = 2 * kc + b_ch;
                ldsm4(bv, bV + (nb2 * 16 + b_row) * 256 + (((ch & 8) | ((ch & 7) ^ lr)) << 4));
                mma_f16(O[2 * nb2], ph, bv[0], bv[1]);
                mma_f16(O[2 * nb2 + 1], ph, bv[2], bv[3]);
            }
        }
        __syncthreads();
        if (t + 2 < 32) {
            fillA((t & 1) ? bK1 : bK0, Kg + (size_t)(t + 2) * 128 * DEMB, DEMB);
            fillA((t & 1) ? bV1 : bV0, Vg + (t + 2) * 128, NPIX);
            CP_COMMIT();
        }
    }

#pragma unroll
    for (int off = 1; off < 4; off <<= 1) {
        l0 += __shfl_xor_sync(0xffffffffu, l0, off);
        l1 += __shfl_xor_sync(0xffffffffu, l1, off);
    }
    const float inv0 = 1.f / l0, inv1 = 1.f / l1;

    const int qg0 = qbase + q0 + (lane >> 2);
#pragma unroll
    for (int nb2 = 0; nb2 < 16; nb2++) {
        int d = nb2 * 8 + 2 * (lane & 3);
        float v0 = O[nb2][0] * inv0, v1 = O[nb2][1] * inv0;
        float v2 = O[nb2][2] * inv1, v3 = O[nb2][3] * inv1;
        __half h0 = __float2half_rn(v0), h1 = __float2half_rn(v1);
        __half h2 = __float2half_rn(v2), h3 = __float2half_rn(v3);
        Oh[(size_t)d * NPIX + qg0] = h0;
        Oh[(size_t)(d + 1) * NPIX + qg0] = h1;
        Oh[(size_t)d * NPIX + qg0 + 8] = h2;
        Oh[(size_t)(d + 1) * NPIX + qg0 + 8] = h3;
        Ol[(size_t)d * NPIX + qg0] = __float2half_rn(v0 - __half2float(h0));
        Ol[(size_t)(d + 1) * NPIX + qg0] = __float2half_rn(v1 - __half2float(h1));
        Ol[(size_t)d * NPIX + qg0 + 8] = __float2half_rn(v2 - __half2float(h2));
        Ol[(size_t)(d + 1) * NPIX + qg0 + 8] = __float2half_rn(v3 - __half2float(h3));
    }
}

// ---------------- launch -----------------------------------------------------
extern "C" void kernel_launch(void* const* d_in, const int* in_sizes, int n_in,
                              void* d_out, int out_size)
{
    (void)in_sizes; (void)n_in; (void)out_size;
    const float* f_rgb   = (const float*)d_in[0];
    const float* f_pl    = (const float*)d_in[1];
    const float* w_q_rgb = (const float*)d_in[2];
    const float* b_q_rgb = (const float*)d_in[3];
    const float* w_k_pl  = (const float*)d_in[4];
    const float* b_k_pl  = (const float*)d_in[5];
    const float* w_v_pl  = (const float*)d_in[6];
    const float* b_v_pl  = (const float*)d_in[7];
    const float* w_q_pl  = (const float*)d_in[8];
    const float* b_q_pl  = (const float*)d_in[9];
    const float* w_k_rgb = (const float*)d_in[10];
    const float* b_k_rgb = (const float*)d_in[11];
    const float* w_v_rgb = (const float*)d_in[12];
    const float* b_v_rgb = (const float*)d_in[13];
    const float* w_proj  = (const float*)d_in[14];
    const float* bn_g    = (const float*)d_in[15];
    const float* bn_b    = (const float*)d_in[16];
    const float* bn_m    = (const float*)d_in[17];
    const float* bn_v    = (const float*)d_in[18];

    __half *hp, *xh, *xl, *wh, *wl;
    cudaGetSymbolAddress((void**)&hp, g_h);
    cudaGetSymbolAddress((void**)&xh, g_xh);
    cudaGetSymbolAddress((void**)&xl, g_xl);
    cudaGetSymbolAddress((void**)&wh, g_wh);
    cudaGetSymbolAddress((void**)&wl, g_wl);

    const int NX = NBATCH * 256 * NPIX;   // per input tensor
    cvt_kernel<<<NX / 2048, 256>>>(f_rgb, xh, xl, NX);
    cvt_kernel<<<NX / 2048, 256>>>(f_pl, xh + NX, xl + NX, NX);

    // weight conversion: 6 proj W (order = ProjTab order) + w_proj
    // input0 (f_rgb): q_rgb, k_rgb, v_rgb ; input1 (f_pl): k_pl, v_pl, q_pl
    const float* wsrc[7] = { w_q_rgb, w_k_rgb, w_v_rgb, w_k_pl, w_v_pl, w_q_pl, w_proj };
    const int wn_[7] = { 32768, 32768, 32768, 32768, 32768, 32768, 65536 };
    int woff = 0;
    for (int i = 0; i < 7; i++) {
        cvt_kernel<<<wn_[i] / 2048, 256>>>(wsrc[i], wh + woff, wl + woff, wn_[i]);
        woff += wn_[i];
    }

    const size_t PL = (size_t)NBATCH * DEMB * NPIX;
    ProjTab pt;
    // p = input*3 + y; planes: Qa=0 Ka=1 Va=2 Qb=3 Kb=4 Vb=5
    int woffs[6] = { 0, 32768, 65536, 98304, 131072, 163840 };
    const float* biases[6] = { b_q_rgb, b_k_rgb, b_v_rgb, b_k_pl, b_v_pl, b_q_pl };
    float scales[6] = { ATT_SCALE, 1.f, 1.f, 1.f, 1.f, ATT_SCALE };
    int vmodes[6] = { 0, 0, 1, 0, 1, 0 };
    int planes[6] = { 0, 4, 5, 1, 2, 3 };  // Qa, Kb, Vb, Ka, Va, Qb
    for (int i = 0; i < 6; i++) {
        pt.woff[i] = woffs[i]; pt.bias[i] = biases[i];
        pt.scale[i] = scales[i]; pt.vmode[i] = vmodes[i];
        pt.out[i] = hp + (size_t)planes[i] * PL;
    }

    cudaFuncSetAttribute(proj_mma, cudaFuncAttributeMaxDynamicSharedMemorySize, GEMM_SMEM);
    proj_mma<<<dim3(32, 3, 16), 256, GEMM_SMEM>>>(pt);

    cudaFuncSetAttribute(attn_kernel, cudaFuncAttributeMaxDynamicSharedMemorySize, ATT_SMEM);
    attn_kernel<<<dim3(NPIX / 128, 2, NBATCH), 256, ATT_SMEM>>>();

    cudaFuncSetAttribute(final_mma, cudaFuncAttributeMaxDynamicSharedMemorySize, GEMM_SMEM);
    final_mma<<<dim3(32, 2, NBATCH), 256, GEMM_SMEM>>>((float*)d_out,
                                                       bn_g, bn_b, bn_m, bn_v);
}

// round 7
// speedup vs baseline: 6.9834x; 1.1034x over previous
#include <cuda_runtime.h>
#include <cuda_fp16.h>
#include <stdint.h>
#include <math.h>

#define NBATCH 8
#define NPIX   4096
#define DEMB   128
#define ATT_SCALE 0.08838834764831845f
#define LOG2E 1.4426950408889634f
#define BN_EPS 1e-5f

// fp16 single planes for attention operands: (dir*3+kind), kind 0 Q,1 K,2 V.
// Q,K stored [n][d]; V stored [d][n]. Q pre-scaled by ATT_SCALE*LOG2E.
__device__ __half g_h[(size_t)6 * NBATCH * DEMB * NPIX];        // 50 MB
// input features converted to hi/lo fp16, layout [input][b][k=256][n=4096]
__device__ __half g_xh[(size_t)2 * NBATCH * 256 * NPIX];        // 33.5 MB
__device__ __half g_xl[(size_t)2 * NBATCH * 256 * NPIX];
// attention output (concat) hi/lo planes [b][256][4096]
__device__ __half g_ch[(size_t)NBATCH * 256 * NPIX];            // 16.8 MB
__device__ __half g_cl[(size_t)NBATCH * 256 * NPIX];
// weights hi/lo: 6 proj W [128][256] at p*32768, then w_proj [256][256] at 196608
__device__ __half g_wh[262144];
__device__ __half g_wl[262144];

// ------------------------------------------------------------- helpers -----
__device__ __forceinline__ uint32_t smem_u32(const void* p) {
    uint32_t a;
    asm("{ .reg .u64 t; cvta.to.shared.u64 t, %1; cvt.u32.u64 %0, t; }" : "=r"(a) : "l"(p));
    return a;
}
__device__ __forceinline__ uint32_t pkh(float a, float b) {
    __half2 h = __floats2half2_rn(a, b);
    return *reinterpret_cast<uint32_t*>(&h);
}
__device__ __forceinline__ void mma_f16(float c[4], const uint32_t a[4],
                                        uint32_t b0, uint32_t b1) {
    asm volatile("mma.sync.aligned.m16n8k16.row.col.f32.f16.f16.f32 "
        "{%0,%1,%2,%3}, {%4,%5,%6,%7}, {%8,%9}, {%0,%1,%2,%3};"
        : "+f"(c[0]), "+f"(c[1]), "+f"(c[2]), "+f"(c[3])
        : "r"(a[0]), "r"(a[1]), "r"(a[2]), "r"(a[3]), "r"(b0), "r"(b1));
}
__device__ __forceinline__ void ldsm4(uint32_t r[4], uint32_t addr) {
    asm volatile("ldmatrix.sync.aligned.m8n8.x4.shared.b16 {%0,%1,%2,%3}, [%4];"
        : "=r"(r[0]), "=r"(r[1]), "=r"(r[2]), "=r"(r[3]) : "r"(addr));
}
__device__ __forceinline__ void ldsm4t(uint32_t r[4], uint32_t addr) {
    asm volatile("ldmatrix.sync.aligned.m8n8.x4.trans.shared.b16 {%0,%1,%2,%3}, [%4];"
        : "=r"(r[0]), "=r"(r[1]), "=r"(r[2]), "=r"(r[3]) : "r"(addr));
}
__device__ __forceinline__ void cpa16(uint32_t s, const void* g) {
    asm volatile("cp.async.cg.shared.global [%0], [%1], 16;" :: "r"(s), "l"(g));
}
#define CP_COMMIT() asm volatile("cp.async.commit_group;" ::: "memory")
#define CP_WAIT(n)  asm volatile("cp.async.wait_group %0;" :: "n"(n) : "memory")

// ---------------- merged fp32 -> fp16 hi/lo converter -----------------------
struct CvtTab {
    const float* src[9];
    __half* dh[9];
    __half* dl[9];
    int blkoff[10];     // block-index prefix (2048 elems per block)
};

__global__ __launch_bounds__(256) void cvt_all(CvtTab t)
{
    int blk = blockIdx.x, seg = 0;
    while (blk >= t.blkoff[seg + 1]) seg++;
    int i = ((blk - t.blkoff[seg]) * 256 + threadIdx.x) * 8;
    const float* src = t.src[seg];
    __half* dh = t.dh[seg];
    __half* dl = t.dl[seg];

    float4 a = *(const float4*)(src + i);
    float4 b = *(const float4*)(src + i + 4);
    float v[8] = {a.x, a.y, a.z, a.w, b.x, b.y, b.z, b.w};
    uint32_t h[4], l[4];
#pragma unroll
    for (int j = 0; j < 4; j++) {
        __half h0 = __float2half_rn(v[2 * j]), h1 = __float2half_rn(v[2 * j + 1]);
        __half2 hh(h0, h1);
        h[j] = *reinterpret_cast<uint32_t*>(&hh);
        l[j] = pkh(v[2 * j] - __half2float(h0), v[2 * j + 1] - __half2float(h1));
    }
    *(uint2*)(dh + i)     = make_uint2(h[0], h[1]);
    *(uint2*)(dh + i + 4) = make_uint2(h[2], h[3]);
    *(uint2*)(dl + i)     = make_uint2(l[0], l[1]);
    *(uint2*)(dl + i + 4) = make_uint2(l[2], l[3]);
}

// ---------------- tensor GEMM constants (K-chunk 32, 2 CTAs/SM) -------------
// X buf: 32 rows x 272B = 8704 per plane; W buf: 128 rows x 80B = 10240 per plane
#define SB_XH 0
#define SB_XL 8704
#define SB_WH 17408
#define SB_WL 27648
#define SB_BUF 37888
#define GEMM_SMEM (2 * SB_BUF)

struct ProjTab {
    int woff[6];
    const float* bias[6];
    float scale[6];
    int vmode[6];           // 0: out [n][d], 1: out [d][n]
    __half* out[6];
};

// proj: Y(128, 4096-tile) = W(128,256) @ X(256,4096) + bias, fp16 out planes
__global__ __launch_bounds__(256, 2) void proj_mma(ProjTab pt)
{
    extern __shared__ char sm[];
    const int tid = threadIdx.x, lane = tid & 31, w = tid >> 5;
    const int nb = blockIdx.x * 128;
    const int input = blockIdx.z >> 3, b = blockIdx.z & 7;
    const int p = input * 3 + blockIdx.y;

    const __half* Xh = g_xh + (size_t)(input * 8 + b) * 256 * NPIX;
    const __half* Xl = g_xl + (size_t)(input * 8 + b) * 256 * NPIX;
    const __half* Wh = g_wh + pt.woff[p];
    const __half* Wl = g_wl + pt.woff[p];
    const float* bias = pt.bias[p];
    const float scale = pt.scale[p];
    const int vmode = pt.vmode[p];
    __half* out = pt.out[p] + (size_t)b * DEMB * NPIX;

    const uint32_t sb = smem_u32(sm);

    auto fill = [&](int c, int s) {
        uint32_t base = sb + s * SB_BUF;
#pragma unroll
        for (int i = 0; i < 2; i++) {   // X: 32 rows x 16 chunks
            int idx = tid + 256 * i, r = idx >> 4, ch = idx & 15;
            const size_t go = (size_t)(c * 32 + r) * NPIX + nb + ch * 8;
            cpa16(base + SB_XH + r * 272 + ch * 16, Xh + go);
            cpa16(base + SB_XL + r * 272 + ch * 16, Xl + go);
        }
#pragma unroll
        for (int i = 0; i < 2; i++) {   // W: 128 rows x 4 chunks
            int idx = tid + 256 * i, m = idx >> 2, ch = idx & 3;
            const size_t go = (size_t)m * 256 + c * 32 + ch * 8;
            cpa16(base + SB_WH + m * 80 + ch * 16, Wh + go);
            cpa16(base + SB_WL + m * 80 + ch * 16, Wl + go);
        }
    };

    fill(0, 0); CP_COMMIT();
    fill(1, 1); CP_COMMIT();

    const int lr = lane & 7, g = lane >> 3;
    const int fr = lr + ((g & 1) << 3), fc = g >> 1;
    const int wm = w >> 2, wn = w & 3;

    float C[4][4][4];
#pragma unroll
    for (int i = 0; i < 4; i++)
#pragma unroll
        for (int j = 0; j < 4; j++)
#pragma unroll
            for (int k = 0; k < 4; k++) C[i][j][k] = 0.f;

    for (int c = 0; c < 8; c++) {
        if (c < 6) { CP_WAIT(1); } else { CP_WAIT(0); }
        __syncthreads();
        const uint32_t base = sb + (c & 1) * SB_BUF;
#pragma unroll
        for (int kt = 0; kt < 2; kt++) {
            uint32_t bh[2][4], bl[2][4];
#pragma unroll
            for (int nh = 0; nh < 2; nh++) {
                uint32_t ad = base + (kt * 16 + fr) * 272 + (wn * 32 + nh * 16 + fc * 8) * 2;
                ldsm4t(bh[nh], ad + SB_XH);
                ldsm4t(bl[nh], ad + SB_XL);
            }
#pragma unroll
            for (int mt = 0; mt < 4; mt++) {
                uint32_t ah[4], al[4];
                uint32_t ad = base + (wm * 64 + mt * 16 + fr) * 80 + (kt * 16 + fc * 8) * 2;
                ldsm4(ah, ad + SB_WH);
                ldsm4(al, ad + SB_WL);
#pragma unroll
                for (int nh = 0; nh < 2; nh++) {
                    mma_f16(C[mt][2 * nh], ah, bh[nh][0], bh[nh][1]);
                    mma_f16(C[mt][2 * nh], ah, bl[nh][0], bl[nh][1]);
                    mma_f16(C[mt][2 * nh], al, bh[nh][0], bh[nh][1]);
                    mma_f16(C[mt][2 * nh + 1], ah, bh[nh][2], bh[nh][3]);
                    mma_f16(C[mt][2 * nh + 1], ah, bl[nh][2], bl[nh][3]);
                    mma_f16(C[mt][2 * nh + 1], al, bh[nh][2], bh[nh][3]);
                }
            }
        }
        __syncthreads();
        if (c + 2 < 8) { fill(c + 2, c & 1); CP_COMMIT(); }
    }

    // epilogue: bias+scale, fp16, stage to target layout (pitch 272B)
    __half* stage = (__half*)sm;
#pragma unroll
    for (int mt = 0; mt < 4; mt++) {
        int m0 = wm * 64 + mt * 16 + (lane >> 2);
        float b0 = bias[m0], b1 = bias[m0 + 8];
#pragma unroll
        for (int nt = 0; nt < 4; nt++) {
            int n = wn * 32 + nt * 8 + 2 * (lane & 3);
            float v0 = (C[mt][nt][0] + b0) * scale;
            float v1 = (C[mt][nt][1] + b0) * scale;
            float v2 = (C[mt][nt][2] + b1) * scale;
            float v3 = (C[mt][nt][3] + b1) * scale;
            if (vmode == 0) {   // stage [n][d]
                stage[n * 136 + m0] = __float2half_rn(v0);
                stage[(n + 1) * 136 + m0] = __float2half_rn(v1);
                stage[n * 136 + m0 + 8] = __float2half_rn(v2);
                stage[(n + 1) * 136 + m0 + 8] = __float2half_rn(v3);
            } else {            // stage [d][n]
                *(uint32_t*)&stage[m0 * 136 + n] = pkh(v0, v1);
                *(uint32_t*)&stage[(m0 + 8) * 136 + n] = pkh(v2, v3);
            }
        }
    }
    __syncthreads();
#pragma unroll
    for (int i = 0; i < 8; i++) {
        int idx = tid + 256 * i, r = idx >> 4, ch = idx & 15;
        uint4 v = *(uint4*)((char*)sm + r * 272 + ch * 16);
        if (vmode == 0)
            *(uint4*)(out + (size_t)(nb + r) * DEMB + ch * 8) = v;
        else
            *(uint4*)(out + (size_t)r * NPIX + nb + ch * 8) = v;
    }
}

// final: out(256,4096) = relu(BN(Wp(256,256) @ comb)) fp32
__global__ __launch_bounds__(256, 2) void final_mma(
    float* __restrict__ Y,
    const float* __restrict__ bng, const float* __restrict__ bnb,
    const float* __restrict__ bnm, const float* __restrict__ bnv)
{
    extern __shared__ char sm[];
    const int tid = threadIdx.x, lane = tid & 31, w = tid >> 5;
    const int nb = blockIdx.x * 128;
    const int mbase = blockIdx.y * 128;
    const int b = blockIdx.z;

    const __half* Xh = g_ch + (size_t)b * 256 * NPIX;
    const __half* Xl = g_cl + (size_t)b * 256 * NPIX;
    const __half* Wh = g_wh + 196608;
    const __half* Wl = g_wl + 196608;
    float* Yb = Y + (size_t)b * 256 * NPIX;

    const uint32_t sb = smem_u32(sm);

    auto fill = [&](int c, int s) {
        uint32_t base = sb + s * SB_BUF;
#pragma unroll
        for (int i = 0; i < 2; i++) {
            int idx = tid + 256 * i, r = idx >> 4, ch = idx & 15;
            const size_t go = (size_t)(c * 32 + r) * NPIX + nb + ch * 8;
            cpa16(base + SB_XH + r * 272 + ch * 16, Xh + go);
            cpa16(base + SB_XL + r * 272 + ch * 16, Xl + go);
        }
#pragma unroll
        for (int i = 0; i < 2; i++) {
            int idx = tid + 256 * i, m = idx >> 2, ch = idx & 3;
            const size_t go = (size_t)(mbase + m) * 256 + c * 32 + ch * 8;
            cpa16(base + SB_WH + m * 80 + ch * 16, Wh + go);
            cpa16(base + SB_WL + m * 80 + ch * 16, Wl + go);
        }
    };

    fill(0, 0); CP_COMMIT();
    fill(1, 1); CP_COMMIT();

    const int lr = lane & 7, g = lane >> 3;
    const int fr = lr + ((g & 1) << 3), fc = g >> 1;
    const int wm = w >> 2, wn = w & 3;

    float C[4][4][4];
#pragma unroll
    for (int i = 0; i < 4; i++)
#pragma unroll
        for (int j = 0; j < 4; j++)
#pragma unroll
            for (int k = 0; k < 4; k++) C[i][j][k] = 0.f;

    for (int c = 0; c < 8; c++) {
        if (c < 6) { CP_WAIT(1); } else { CP_WAIT(0); }
        __syncthreads();
        const uint32_t base = sb + (c & 1) * SB_BUF;
#pragma unroll
        for (int kt = 0; kt < 2; kt++) {
            uint32_t bh[2][4], bl[2][4];
#pragma unroll
            for (int nh = 0; nh < 2; nh++) {
                uint32_t ad = base + (kt * 16 + fr) * 272 + (wn * 32 + nh * 16 + fc * 8) * 2;
                ldsm4t(bh[nh], ad + SB_XH);
                ldsm4t(bl[nh], ad + SB_XL);
            }
#pragma unroll
            for (int mt = 0; mt < 4; mt++) {
                uint32_t ah[4], al[4];
                uint32_t ad = base + (wm * 64 + mt * 16 + fr) * 80 + (kt * 16 + fc * 8) * 2;
                ldsm4(ah, ad + SB_WH);
                ldsm4(al, ad + SB_WL);
#pragma unroll
                for (int nh = 0; nh < 2; nh++) {
                    mma_f16(C[mt][2 * nh], ah, bh[nh][0], bh[nh][1]);
                    mma_f16(C[mt][2 * nh], ah, bl[nh][0], bl[nh][1]);
                    mma_f16(C[mt][2 * nh], al, bh[nh][0], bh[nh][1]);
                    mma_f16(C[mt][2 * nh + 1], ah, bh[nh][2], bh[nh][3]);
                    mma_f16(C[mt][2 * nh + 1], ah, bl[nh][2], bl[nh][3]);
                    mma_f16(C[mt][2 * nh + 1], al, bh[nh][2], bh[nh][3]);
                }
            }
        }
        __syncthreads();
        if (c + 2 < 8) { fill(c + 2, c & 1); CP_COMMIT(); }
    }

    // BN + ReLU, stage fp32 [m][n] pitch 132 floats, coalesced STG
    float* stage = (float*)sm;
#pragma unroll
    for (int mt = 0; mt < 4; mt++) {
        int ml = wm * 64 + mt * 16 + (lane >> 2);
        int m0 = mbase + ml, m1 = m0 + 8;
        float i0 = bng[m0] * rsqrtf(bnv[m0] + BN_EPS);
        float s0 = bnb[m0] - bnm[m0] * i0;
        float i1 = bng[m1] * rsqrtf(bnv[m1] + BN_EPS);
        float s1 = bnb[m1] - bnm[m1] * i1;
#pragma unroll
        for (int nt = 0; nt < 4; nt++) {
            int n = wn * 32 + nt * 8 + 2 * (lane & 3);
            stage[ml * 132 + n]       = fmaxf(fmaf(C[mt][nt][0], i0, s0), 0.f);
            stage[ml * 132 + n + 1]   = fmaxf(fmaf(C[mt][nt][1], i0, s0), 0.f);
            stage[(ml + 8) * 132 + n]     = fmaxf(fmaf(C[mt][nt][2], i1, s1), 0.f);
            stage[(ml + 8) * 132 + n + 1] = fmaxf(fmaf(C[mt][nt][3], i1, s1), 0.f);
        }
    }
    __syncthreads();
#pragma unroll
    for (int i = 0; i < 16; i++) {
        int idx = tid + 256 * i, r = idx >> 5, ch = idx & 31;
        float4 v = *(float4*)((char*)sm + r * 528 + ch * 16);
        *(float4*)&Yb[(size_t)(mbase + r) * NPIX + nb + ch * 4] = v;
    }
}

// ---------------- warp-MMA flash attention (fp16, double-buffered) ----------
#define ATT_SMEM (5 * 32768)

__global__ __launch_bounds__(256, 1) void attn_kernel()
{
    extern __shared__ char sm[];
    const int tid = threadIdx.x, lane = tid & 31, w = tid >> 5;
    const int qt = blockIdx.x, dir = blockIdx.y, b = blockIdx.z;
    const int qbase = qt * 128;
    const size_t PLANE = (size_t)DEMB * NPIX;

    const __half* Qg = g_h + ((size_t)(dir * 3 + 0) * NBATCH + b) * PLANE;
    const __half* Kg = g_h + ((size_t)(dir * 3 + 1) * NBATCH + b) * PLANE;
    const __half* Vg = g_h + ((size_t)(dir * 3 + 2) * NBATCH + b) * PLANE;
    __half* Oh = g_ch + ((size_t)b * 256 + dir * 128) * NPIX;
    __half* Ol = g_cl + ((size_t)b * 256 + dir * 128) * NPIX;

    const uint32_t bQ = smem_u32(sm);
    const uint32_t bK0 = bQ + 32768, bK1 = bQ + 65536;
    const uint32_t bV0 = bQ + 98304, bV1 = bQ + 131072;

    auto fillA = [&](uint32_t dst, const __half* src, int rstride) {
#pragma unroll
        for (int i = 0; i < 8; i++) {
            int idx = tid + 256 * i;
            int r = idx >> 4, c = idx & 15;
            int ch = (c & 8) | ((c & 7) ^ (r & 7));
            cpa16(dst + r * 256 + ch * 16, src + (size_t)r * rstride + c * 8);
        }
    };

    fillA(bQ, Qg + (size_t)qbase * DEMB, DEMB);           CP_COMMIT();
    fillA(bK0, Kg, DEMB); fillA(bV0, Vg, NPIX);           CP_COMMIT();
    fillA(bK1, Kg + (size_t)128 * DEMB, DEMB);
    fillA(bV1, Vg + 128, NPIX);                           CP_COMMIT();

    const int lr = lane & 7, g = lane >> 3;
    const int a_row = lr + ((g & 1) << 3), a_ch = g >> 1;
    const int b_row = lr + ((g >> 1) << 3), b_ch = g & 1;
    const int q0 = 16 * w;

    CP_WAIT(2);
    __syncthreads();

    uint32_t qf[8][4];
#pragma unroll
    for (int k = 0; k < 8; k++) {
        int ch = 2 * k + a_ch;
        ldsm4(qf[k], bQ + (q0 + a_row) * 256 + (((ch & 8) | ((ch & 7) ^ lr)) << 4));
    }

    float O[16][4];
#pragma unroll
    for (int i = 0; i < 16; i++)
#pragma unroll
        for (int j = 0; j < 4; j++) O[i][j] = 0.f;
    float l0 = 0.f, l1 = 0.f;

    for (int t = 0; t < 32; t++) {
        if (t < 30) { CP_WAIT(1); } else { CP_WAIT(0); }
        __syncthreads();
        const uint32_t bK = (t & 1) ? bK1 : bK0;
        const uint32_t bV = (t & 1) ? bV1 : bV0;

        // ---- full S tile: d-outer, kc-inner -> 16 independent MMA chains ----
        float S[16][4];
#pragma unroll
        for (int i = 0; i < 16; i++)
#pragma unroll
            for (int j = 0; j < 4; j++) S[i][j] = 0.f;
#pragma unroll
        for (int d = 0; d < 8; d++) {
            int ch = 2 * d + b_ch;
            uint32_t co = ((ch & 8) | ((ch & 7) ^ lr)) << 4;
#pragma unroll
            for (int kc = 0; kc < 8; kc++) {
                uint32_t bk[4];
                ldsm4(bk, bK + (kc * 16 + b_row) * 256 + co);
                mma_f16(S[2 * kc], qf[d], bk[0], bk[1]);
                mma_f16(S[2 * kc + 1], qf[d], bk[2], bk[3]);
            }
        }

        // ---- softmax: exp2 on all 128 values (Q pre-scaled by log2e) ----
        uint32_t ph[8][4];
#pragma unroll
        for (int kc = 0; kc < 8; kc++) {
            float* s0 = S[2 * kc];
            float* s1 = S[2 * kc + 1];
            float e00 = exp2f(s0[0]), e01 = exp2f(s0[1]);
            float e02 = exp2f(s0[2]), e03 = exp2f(s0[3]);
            float e10 = exp2f(s1[0]), e11 = exp2f(s1[1]);
            float e12 = exp2f(s1[2]), e13 = exp2f(s1[3]);
            l0 += e00 + e01 + e10 + e11;
            l1 += e02 + e03 + e12 + e13;
            ph[kc][0] = pkh(e00, e01); ph[kc][1] = pkh(e02, e03);
            ph[kc][2] = pkh(e10, e11); ph[kc][3] = pkh(e12, e13);
        }

        // ---- O += P V : kc-outer, nb-inner (16 chains) ----
#pragma unroll
        for (int kc = 0; kc < 8; kc++) {
            int ch = 2 * kc + b_ch;
            uint32_t co = ((ch & 8) | ((ch & 7) ^ lr)) << 4;
#pragma unroll
            for (int nb2 = 0; nb2 < 8; nb2++) {
                uint32_t bv[4];
                ldsm4(bv, bV + (nb2 * 16 + b_row) * 256 + co);
                mma_f16(O[2 * nb2], ph[kc], bv[0], bv[1]);
                mma_f16(O[2 * nb2 + 1], ph[kc], bv[2], bv[3]);
            }
        }
        __syncthreads();
        if (t + 2 < 32) {
            fillA((t & 1) ? bK1 : bK0, Kg + (size_t)(t + 2) * 128 * DEMB, DEMB);
            fillA((t & 1) ? bV1 : bV0, Vg + (t + 2) * 128, NPIX);
            CP_COMMIT();
        }
    }

#pragma unroll
    for (int off = 1; off < 4; off <<= 1) {
        l0 += __shfl_xor_sync(0xffffffffu, l0, off);
        l1 += __shfl_xor_sync(0xffffffffu, l1, off);
    }
    const float inv0 = 1.f / l0, inv1 = 1.f / l1;

    const int qg0 = qbase + q0 + (lane >> 2);
#pragma unroll
    for (int nb2 = 0; nb2 < 16; nb2++) {
        int d = nb2 * 8 + 2 * (lane & 3);
        float v0 = O[nb2][0] * inv0, v1 = O[nb2][1] * inv0;
        float v2 = O[nb2][2] * inv1, v3 = O[nb2][3] * inv1;
        __half h0 = __float2half_rn(v0), h1 = __float2half_rn(v1);
        __half h2 = __float2half_rn(v2), h3 = __float2half_rn(v3);
        Oh[(size_t)d * NPIX + qg0] = h0;
        Oh[(size_t)(d + 1) * NPIX + qg0] = h1;
        Oh[(size_t)d * NPIX + qg0 + 8] = h2;
        Oh[(size_t)(d + 1) * NPIX + qg0 + 8] = h3;
        Ol[(size_t)d * NPIX + qg0] = __float2half_rn(v0 - __half2float(h0));
        Ol[(size_t)(d + 1) * NPIX + qg0] = __float2half_rn(v1 - __half2float(h1));
        Ol[(size_t)d * NPIX + qg0 + 8] = __float2half_rn(v2 - __half2float(h2));
        Ol[(size_t)(d + 1) * NPIX + qg0 + 8] = __float2half_rn(v3 - __half2float(h3));
    }
}

// ---------------- launch -----------------------------------------------------
extern "C" void kernel_launch(void* const* d_in, const int* in_sizes, int n_in,
                              void* d_out, int out_size)
{
    (void)in_sizes; (void)n_in; (void)out_size;
    const float* f_rgb   = (const float*)d_in[0];
    const float* f_pl    = (const float*)d_in[1];
    const float* w_q_rgb = (const float*)d_in[2];
    const float* b_q_rgb = (const float*)d_in[3];
    const float* w_k_pl  = (const float*)d_in[4];
    const float* b_k_pl  = (const float*)d_in[5];
    const float* w_v_pl  = (const float*)d_in[6];
    const float* b_v_pl  = (const float*)d_in[7];
    const float* w_q_pl  = (const float*)d_in[8];
    const float* b_q_pl  = (const float*)d_in[9];
    const float* w_k_rgb = (const float*)d_in[10];
    const float* b_k_rgb = (const float*)d_in[11];
    const float* w_v_rgb = (const float*)d_in[12];
    const float* b_v_rgb = (const float*)d_in[13];
    const float* w_proj  = (const float*)d_in[14];
    const float* bn_g    = (const float*)d_in[15];
    const float* bn_b    = (const float*)d_in[16];
    const float* bn_m    = (const float*)d_in[17];
    const float* bn_v    = (const float*)d_in[18];

    __half *hp, *xh, *xl, *wh, *wl;
    cudaGetSymbolAddress((void**)&hp, g_h);
    cudaGetSymbolAddress((void**)&xh, g_xh);
    cudaGetSymbolAddress((void**)&xl, g_xl);
    cudaGetSymbolAddress((void**)&wh, g_wh);
    cudaGetSymbolAddress((void**)&wl, g_wl);

    const int NX = NBATCH * 256 * NPIX;
    // one merged convert launch: 2 feature tensors + 7 weights
    CvtTab ct;
    const float* srcs[9] = { f_rgb, f_pl, w_q_rgb, w_k_rgb, w_v_rgb,
                             w_k_pl, w_v_pl, w_q_pl, w_proj };
    int sizes[9] = { NX, NX, 32768, 32768, 32768, 32768, 32768, 32768, 65536 };
    __half* dhs[9] = { xh, xh + NX, wh, wh + 32768, wh + 65536,
                       wh + 98304, wh + 131072, wh + 163840, wh + 196608 };
    __half* dls[9] = { xl, xl + NX, wl, wl + 32768, wl + 65536,
                       wl + 98304, wl + 131072, wl + 163840, wl + 196608 };
    int off = 0;
    for (int i = 0; i < 9; i++) {
        ct.src[i] = srcs[i]; ct.dh[i] = dhs[i]; ct.dl[i] = dls[i];
        ct.blkoff[i] = off;
        off += sizes[i] / 2048;
    }
    ct.blkoff[9] = off;
    cvt_all<<<off, 256>>>(ct);

    const size_t PL = (size_t)NBATCH * DEMB * NPIX;
    ProjTab pt;
    int woffs[6] = { 0, 32768, 65536, 98304, 131072, 163840 };
    const float* biases[6] = { b_q_rgb, b_k_rgb, b_v_rgb, b_k_pl, b_v_pl, b_q_pl };
    float scales[6] = { ATT_SCALE * LOG2E, 1.f, 1.f, 1.f, 1.f, ATT_SCALE * LOG2E };
    int vmodes[6] = { 0, 0, 1, 0, 1, 0 };
    int planes[6] = { 0, 4, 5, 1, 2, 3 };  // Qa, Kb, Vb, Ka, Va, Qb
    for (int i = 0; i < 6; i++) {
        pt.woff[i] = woffs[i]; pt.bias[i] = biases[i];
        pt.scale[i] = scales[i]; pt.vmode[i] = vmodes[i];
        pt.out[i] = hp + (size_t)planes[i] * PL;
    }

    cudaFuncSetAttribute(proj_mma, cudaFuncAttributeMaxDynamicSharedMemorySize, GEMM_SMEM);
    proj_mma<<<dim3(32, 3, 16), 256, GEMM_SMEM>>>(pt);

    cudaFuncSetAttribute(attn_kernel, cudaFuncAttributeMaxDynamicSharedMemorySize, ATT_SMEM);
    attn_kernel<<<dim3(NPIX / 128, 2, NBATCH), 256, ATT_SMEM>>>();

    cudaFuncSetAttribute(final_mma, cudaFuncAttributeMaxDynamicSharedMemorySize, GEMM_SMEM);
    final_mma<<<dim3(32, 2, NBATCH), 256, GEMM_SMEM>>>((float*)d_out,
                                                       bn_g, bn_b, bn_m, bn_v);
}

// round 8
// speedup vs baseline: 7.1015x; 1.0169x over previous
#include <cuda_runtime.h>
#include <cuda_fp16.h>
#include <stdint.h>
#include <math.h>

#define NBATCH 8
#define NPIX   4096
#define DEMB   128
#define ATT_SCALE 0.08838834764831845f
#define LOG2E 1.4426950408889634f
#define BN_EPS 1e-5f

// fp16 single planes for attention operands: (dir*3+kind), kind 0 Q,1 K,2 V.
// Q,K stored [n][d]; V stored [d][n]. Q pre-scaled by ATT_SCALE*LOG2E.
__device__ __half g_h[(size_t)6 * NBATCH * DEMB * NPIX];        // 50 MB
// input features converted to hi/lo fp16, layout [input][b][k=256][n=4096]
__device__ __half g_xh[(size_t)2 * NBATCH * 256 * NPIX];        // 33.5 MB
__device__ __half g_xl[(size_t)2 * NBATCH * 256 * NPIX];
// attention output (concat) fp16 [b][256][4096]
__device__ __half g_ch[(size_t)NBATCH * 256 * NPIX];            // 16.8 MB
// weights hi/lo: 6 proj W [128][256] at p*32768, then w_proj [256][256] at 196608
__device__ __half g_wh[262144];
__device__ __half g_wl[262144];

// ------------------------------------------------------------- helpers -----
__device__ __forceinline__ uint32_t smem_u32(const void* p) {
    uint32_t a;
    asm("{ .reg .u64 t; cvta.to.shared.u64 t, %1; cvt.u32.u64 %0, t; }" : "=r"(a) : "l"(p));
    return a;
}
__device__ __forceinline__ uint32_t pkh(float a, float b) {
    __half2 h = __floats2half2_rn(a, b);
    return *reinterpret_cast<uint32_t*>(&h);
}
__device__ __forceinline__ void mma_f16(float c[4], const uint32_t a[4],
                                        uint32_t b0, uint32_t b1) {
    asm volatile("mma.sync.aligned.m16n8k16.row.col.f32.f16.f16.f32 "
        "{%0,%1,%2,%3}, {%4,%5,%6,%7}, {%8,%9}, {%0,%1,%2,%3};"
        : "+f"(c[0]), "+f"(c[1]), "+f"(c[2]), "+f"(c[3])
        : "r"(a[0]), "r"(a[1]), "r"(a[2]), "r"(a[3]), "r"(b0), "r"(b1));
}
__device__ __forceinline__ void ldsm4(uint32_t r[4], uint32_t addr) {
    asm volatile("ldmatrix.sync.aligned.m8n8.x4.shared.b16 {%0,%1,%2,%3}, [%4];"
        : "=r"(r[0]), "=r"(r[1]), "=r"(r[2]), "=r"(r[3]) : "r"(addr));
}
__device__ __forceinline__ void ldsm4t(uint32_t r[4], uint32_t addr) {
    asm volatile("ldmatrix.sync.aligned.m8n8.x4.trans.shared.b16 {%0,%1,%2,%3}, [%4];"
        : "=r"(r[0]), "=r"(r[1]), "=r"(r[2]), "=r"(r[3]) : "r"(addr));
}
__device__ __forceinline__ void cpa16(uint32_t s, const void* g) {
    asm volatile("cp.async.cg.shared.global [%0], [%1], 16;" :: "r"(s), "l"(g));
}
#define CP_COMMIT() asm volatile("cp.async.commit_group;" ::: "memory")
#define CP_WAIT(n)  asm volatile("cp.async.wait_group %0;" :: "n"(n) : "memory")

// ---------------- merged fp32 -> fp16 hi/lo converter -----------------------
struct CvtTab {
    const float* src[9];
    __half* dh[9];
    __half* dl[9];
    int blkoff[10];     // block-index prefix (2048 elems per block)
};

__global__ __launch_bounds__(256) void cvt_all(CvtTab t)
{
    int blk = blockIdx.x, seg = 0;
    while (blk >= t.blkoff[seg + 1]) seg++;
    int i = ((blk - t.blkoff[seg]) * 256 + threadIdx.x) * 8;
    const float* src = t.src[seg];
    __half* dh = t.dh[seg];
    __half* dl = t.dl[seg];

    float4 a = *(const float4*)(src + i);
    float4 b = *(const float4*)(src + i + 4);
    float v[8] = {a.x, a.y, a.z, a.w, b.x, b.y, b.z, b.w};
    uint32_t h[4], l[4];
#pragma unroll
    for (int j = 0; j < 4; j++) {
        __half h0 = __float2half_rn(v[2 * j]), h1 = __float2half_rn(v[2 * j + 1]);
        __half2 hh(h0, h1);
        h[j] = *reinterpret_cast<uint32_t*>(&hh);
        l[j] = pkh(v[2 * j] - __half2float(h0), v[2 * j + 1] - __half2float(h1));
    }
    *(uint2*)(dh + i)     = make_uint2(h[0], h[1]);
    *(uint2*)(dh + i + 4) = make_uint2(h[2], h[3]);
    *(uint2*)(dl + i)     = make_uint2(l[0], l[1]);
    *(uint2*)(dl + i + 4) = make_uint2(l[2], l[3]);
}

// ---------------- proj GEMM constants (hi/lo, K-chunk 32) -------------------
#define SB_XH 0
#define SB_XL 8704
#define SB_WH 17408
#define SB_WL 27648
#define SB_BUF 37888
#define GEMM_SMEM (2 * SB_BUF)

struct ProjTab {
    int woff[6];
    const float* bias[6];
    float scale[6];
    int vmode[6];           // 0: out [n][d], 1: out [d][n]
    __half* out[6];
};

// proj: Y(128, 4096-tile) = W(128,256) @ X(256,4096) + bias, fp16 out planes
__global__ __launch_bounds__(256, 2) void proj_mma(ProjTab pt)
{
    extern __shared__ char sm[];
    const int tid = threadIdx.x, lane = tid & 31, w = tid >> 5;
    const int nb = blockIdx.x * 128;
    const int input = blockIdx.z >> 3, b = blockIdx.z & 7;
    const int p = input * 3 + blockIdx.y;

    const __half* Xh = g_xh + (size_t)(input * 8 + b) * 256 * NPIX;
    const __half* Xl = g_xl + (size_t)(input * 8 + b) * 256 * NPIX;
    const __half* Wh = g_wh + pt.woff[p];
    const __half* Wl = g_wl + pt.woff[p];
    const float* bias = pt.bias[p];
    const float scale = pt.scale[p];
    const int vmode = pt.vmode[p];
    __half* out = pt.out[p] + (size_t)b * DEMB * NPIX;

    const uint32_t sb = smem_u32(sm);

    auto fill = [&](int c, int s) {
        uint32_t base = sb + s * SB_BUF;
#pragma unroll
        for (int i = 0; i < 2; i++) {   // X: 32 rows x 16 chunks
            int idx = tid + 256 * i, r = idx >> 4, ch = idx & 15;
            const size_t go = (size_t)(c * 32 + r) * NPIX + nb + ch * 8;
            cpa16(base + SB_XH + r * 272 + ch * 16, Xh + go);
            cpa16(base + SB_XL + r * 272 + ch * 16, Xl + go);
        }
#pragma unroll
        for (int i = 0; i < 2; i++) {   // W: 128 rows x 4 chunks
            int idx = tid + 256 * i, m = idx >> 2, ch = idx & 3;
            const size_t go = (size_t)m * 256 + c * 32 + ch * 8;
            cpa16(base + SB_WH + m * 80 + ch * 16, Wh + go);
            cpa16(base + SB_WL + m * 80 + ch * 16, Wl + go);
        }
    };

    fill(0, 0); CP_COMMIT();
    fill(1, 1); CP_COMMIT();

    const int lr = lane & 7, g = lane >> 3;
    const int fr = lr + ((g & 1) << 3), fc = g >> 1;
    const int wm = w >> 2, wn = w & 3;

    float C[4][4][4];
#pragma unroll
    for (int i = 0; i < 4; i++)
#pragma unroll
        for (int j = 0; j < 4; j++)
#pragma unroll
            for (int k = 0; k < 4; k++) C[i][j][k] = 0.f;

    for (int c = 0; c < 8; c++) {
        if (c < 6) { CP_WAIT(1); } else { CP_WAIT(0); }
        __syncthreads();
        const uint32_t base = sb + (c & 1) * SB_BUF;
#pragma unroll
        for (int kt = 0; kt < 2; kt++) {
            uint32_t bh[2][4], bl[2][4];
#pragma unroll
            for (int nh = 0; nh < 2; nh++) {
                uint32_t ad = base + (kt * 16 + fr) * 272 + (wn * 32 + nh * 16 + fc * 8) * 2;
                ldsm4t(bh[nh], ad + SB_XH);
                ldsm4t(bl[nh], ad + SB_XL);
            }
#pragma unroll
            for (int mt = 0; mt < 4; mt++) {
                uint32_t ah[4], al[4];
                uint32_t ad = base + (wm * 64 + mt * 16 + fr) * 80 + (kt * 16 + fc * 8) * 2;
                ldsm4(ah, ad + SB_WH);
                ldsm4(al, ad + SB_WL);
#pragma unroll
                for (int nh = 0; nh < 2; nh++) {
                    mma_f16(C[mt][2 * nh], ah, bh[nh][0], bh[nh][1]);
                    mma_f16(C[mt][2 * nh], ah, bl[nh][0], bl[nh][1]);
                    mma_f16(C[mt][2 * nh], al, bh[nh][0], bh[nh][1]);
                    mma_f16(C[mt][2 * nh + 1], ah, bh[nh][2], bh[nh][3]);
                    mma_f16(C[mt][2 * nh + 1], ah, bl[nh][2], bl[nh][3]);
                    mma_f16(C[mt][2 * nh + 1], al, bh[nh][2], bh[nh][3]);
                }
            }
        }
        __syncthreads();
        if (c + 2 < 8) { fill(c + 2, c & 1); CP_COMMIT(); }
    }

    // epilogue: bias+scale, fp16, stage to target layout (pitch 272B)
    __half* stage = (__half*)sm;
#pragma unroll
    for (int mt = 0; mt < 4; mt++) {
        int m0 = wm * 64 + mt * 16 + (lane >> 2);
        float b0 = bias[m0], b1 = bias[m0 + 8];
#pragma unroll
        for (int nt = 0; nt < 4; nt++) {
            int n = wn * 32 + nt * 8 + 2 * (lane & 3);
            float v0 = (C[mt][nt][0] + b0) * scale;
            float v1 = (C[mt][nt][1] + b0) * scale;
            float v2 = (C[mt][nt][2] + b1) * scale;
            float v3 = (C[mt][nt][3] + b1) * scale;
            if (vmode == 0) {   // stage [n][d]
                stage[n * 136 + m0] = __float2half_rn(v0);
                stage[(n + 1) * 136 + m0] = __float2half_rn(v1);
                stage[n * 136 + m0 + 8] = __float2half_rn(v2);
                stage[(n + 1) * 136 + m0 + 8] = __float2half_rn(v3);
            } else {            // stage [d][n]
                *(uint32_t*)&stage[m0 * 136 + n] = pkh(v0, v1);
                *(uint32_t*)&stage[(m0 + 8) * 136 + n] = pkh(v2, v3);
            }
        }
    }
    __syncthreads();
#pragma unroll
    for (int i = 0; i < 8; i++) {
        int idx = tid + 256 * i, r = idx >> 4, ch = idx & 15;
        uint4 v = *(uint4*)((char*)sm + r * 272 + ch * 16);
        if (vmode == 0)
            *(uint4*)(out + (size_t)(nb + r) * DEMB + ch * 8) = v;
        else
            *(uint4*)(out + (size_t)r * NPIX + nb + ch * 8) = v;
    }
}

// ---------------- final GEMM (1-term fp16): out = relu(BN(Wp @ comb)) -------
#define FB_XH 0
#define FB_WH 8704
#define FB_BUF 18944
#define FINAL_SMEM 67584    // epilogue stage (128 rows x 528B) dominates

__global__ __launch_bounds__(256, 2) void final_mma(
    float* __restrict__ Y,
    const float* __restrict__ bng, const float* __restrict__ bnb,
    const float* __restrict__ bnm, const float* __restrict__ bnv)
{
    extern __shared__ char sm[];
    const int tid = threadIdx.x, lane = tid & 31, w = tid >> 5;
    const int nb = blockIdx.x * 128;
    const int mbase = blockIdx.y * 128;
    const int b = blockIdx.z;

    const __half* Xh = g_ch + (size_t)b * 256 * NPIX;
    const __half* Wh = g_wh + 196608;
    float* Yb = Y + (size_t)b * 256 * NPIX;

    const uint32_t sb = smem_u32(sm);

    auto fill = [&](int c, int s) {
        uint32_t base = sb + s * FB_BUF;
#pragma unroll
        for (int i = 0; i < 2; i++) {
            int idx = tid + 256 * i, r = idx >> 4, ch = idx & 15;
            cpa16(base + FB_XH + r * 272 + ch * 16,
                  Xh + (size_t)(c * 32 + r) * NPIX + nb + ch * 8);
        }
#pragma unroll
        for (int i = 0; i < 2; i++) {
            int idx = tid + 256 * i, m = idx >> 2, ch = idx & 3;
            cpa16(base + FB_WH + m * 80 + ch * 16,
                  Wh + (size_t)(mbase + m) * 256 + c * 32 + ch * 8);
        }
    };

    fill(0, 0); CP_COMMIT();
    fill(1, 1); CP_COMMIT();

    const int lr = lane & 7, g = lane >> 3;
    const int fr = lr + ((g & 1) << 3), fc = g >> 1;
    const int wm = w >> 2, wn = w & 3;

    float C[4][4][4];
#pragma unroll
    for (int i = 0; i < 4; i++)
#pragma unroll
        for (int j = 0; j < 4; j++)
#pragma unroll
            for (int k = 0; k < 4; k++) C[i][j][k] = 0.f;

    for (int c = 0; c < 8; c++) {
        if (c < 6) { CP_WAIT(1); } else { CP_WAIT(0); }
        __syncthreads();
        const uint32_t base = sb + (c & 1) * FB_BUF;
#pragma unroll
        for (int kt = 0; kt < 2; kt++) {
            uint32_t bh[2][4];
#pragma unroll
            for (int nh = 0; nh < 2; nh++)
                ldsm4t(bh[nh], base + FB_XH + (kt * 16 + fr) * 272 +
                               (wn * 32 + nh * 16 + fc * 8) * 2);
#pragma unroll
            for (int mt = 0; mt < 4; mt++) {
                uint32_t ah[4];
                ldsm4(ah, base + FB_WH + (wm * 64 + mt * 16 + fr) * 80 +
                          (kt * 16 + fc * 8) * 2);
#pragma unroll
                for (int nh = 0; nh < 2; nh++) {
                    mma_f16(C[mt][2 * nh], ah, bh[nh][0], bh[nh][1]);
                    mma_f16(C[mt][2 * nh + 1], ah, bh[nh][2], bh[nh][3]);
                }
            }
        }
        __syncthreads();
        if (c + 2 < 8) { fill(c + 2, c & 1); CP_COMMIT(); }
    }

    // BN + ReLU, stage fp32 [m][n] pitch 132 floats, coalesced STG
    float* stage = (float*)sm;
#pragma unroll
    for (int mt = 0; mt < 4; mt++) {
        int ml = wm * 64 + mt * 16 + (lane >> 2);
        int m0 = mbase + ml, m1 = m0 + 8;
        float i0 = bng[m0] * rsqrtf(bnv[m0] + BN_EPS);
        float s0 = bnb[m0] - bnm[m0] * i0;
        float i1 = bng[m1] * rsqrtf(bnv[m1] + BN_EPS);
        float s1 = bnb[m1] - bnm[m1] * i1;
#pragma unroll
        for (int nt = 0; nt < 4; nt++) {
            int n = wn * 32 + nt * 8 + 2 * (lane & 3);
            stage[ml * 132 + n]       = fmaxf(fmaf(C[mt][nt][0], i0, s0), 0.f);
            stage[ml * 132 + n + 1]   = fmaxf(fmaf(C[mt][nt][1], i0, s0), 0.f);
            stage[(ml + 8) * 132 + n]     = fmaxf(fmaf(C[mt][nt][2], i1, s1), 0.f);
            stage[(ml + 8) * 132 + n + 1] = fmaxf(fmaf(C[mt][nt][3], i1, s1), 0.f);
        }
    }
    __syncthreads();
#pragma unroll
    for (int i = 0; i < 16; i++) {
        int idx = tid + 256 * i, r = idx >> 5, ch = idx & 31;
        float4 v = *(float4*)((char*)sm + r * 528 + ch * 16);
        *(float4*)&Yb[(size_t)(mbase + r) * NPIX + nb + ch * 4] = v;
    }
}

// ---------------- warp-MMA flash attention (BQ=64, 128 threads) -------------
// smem: Q 16KB | K0 K1 V0 V1 32KB each = 144KB; 1 CTA/SM, grid 1024 (~7 waves)
#define ATT_SMEM (16384 + 4 * 32768)

__global__ __launch_bounds__(128, 1) void attn_kernel()
{
    extern __shared__ char sm[];
    const int tid = threadIdx.x, lane = tid & 31, w = tid >> 5;
    const int qt = blockIdx.x, dir = blockIdx.y, b = blockIdx.z;
    const int qbase = qt * 64;
    const size_t PLANE = (size_t)DEMB * NPIX;

    const __half* Qg = g_h + ((size_t)(dir * 3 + 0) * NBATCH + b) * PLANE;
    const __half* Kg = g_h + ((size_t)(dir * 3 + 1) * NBATCH + b) * PLANE;
    const __half* Vg = g_h + ((size_t)(dir * 3 + 2) * NBATCH + b) * PLANE;
    __half* Oh = g_ch + ((size_t)b * 256 + dir * 128) * NPIX;

    const uint32_t bQ = smem_u32(sm);
    const uint32_t bK0 = bQ + 16384, bK1 = bQ + 49152;
    const uint32_t bV0 = bQ + 81920, bV1 = bQ + 114688;

    // 128x128 tile fill, 16B-chunk XOR swizzle (128 threads, 16 iters)
    auto fillA = [&](uint32_t dst, const __half* src, int rstride) {
#pragma unroll
        for (int i = 0; i < 16; i++) {
            int idx = tid + 128 * i;
            int r = idx >> 4, c = idx & 15;
            int ch = (c & 8) | ((c & 7) ^ (r & 7));
            cpa16(dst + r * 256 + ch * 16, src + (size_t)r * rstride + c * 8);
        }
    };
    // 64-row Q tile fill
    auto fillQ = [&]() {
#pragma unroll
        for (int i = 0; i < 8; i++) {
            int idx = tid + 128 * i;
            int r = idx >> 4, c = idx & 15;
            int ch = (c & 8) | ((c & 7) ^ (r & 7));
            cpa16(bQ + r * 256 + ch * 16, Qg + (size_t)(qbase + r) * DEMB + c * 8);
        }
    };

    fillQ();                                              CP_COMMIT();
    fillA(bK0, Kg, DEMB); fillA(bV0, Vg, NPIX);           CP_COMMIT();
    fillA(bK1, Kg + (size_t)128 * DEMB, DEMB);
    fillA(bV1, Vg + 128, NPIX);                           CP_COMMIT();

    const int lr = lane & 7, g = lane >> 3;
    const int a_row = lr + ((g & 1) << 3), a_ch = g >> 1;
    const int b_row = lr + ((g >> 1) << 3), b_ch = g & 1;
    const int q0 = 16 * w;

    CP_WAIT(2);
    __syncthreads();

    uint32_t qf[8][4];
#pragma unroll
    for (int k = 0; k < 8; k++) {
        int ch = 2 * k + a_ch;
        ldsm4(qf[k], bQ + (q0 + a_row) * 256 + (((ch & 8) | ((ch & 7) ^ lr)) << 4));
    }

    float O[16][4];
#pragma unroll
    for (int i = 0; i < 16; i++)
#pragma unroll
        for (int j = 0; j < 4; j++) O[i][j] = 0.f;
    float l0 = 0.f, l1 = 0.f;

    for (int t = 0; t < 32; t++) {
        if (t < 30) { CP_WAIT(1); } else { CP_WAIT(0); }
        __syncthreads();
        const uint32_t bK = (t & 1) ? bK1 : bK0;
        const uint32_t bV = (t & 1) ? bV1 : bV0;

        // ---- full S tile: d-outer, kc-inner -> 16 independent MMA chains ----
        float S[16][4];
#pragma unroll
        for (int i = 0; i < 16; i++)
#pragma unroll
            for (int j = 0; j < 4; j++) S[i][j] = 0.f;
#pragma unroll
        for (int d = 0; d < 8; d++) {
            int ch = 2 * d + b_ch;
            uint32_t co = ((ch & 8) | ((ch & 7) ^ lr)) << 4;
#pragma unroll
            for (int kc = 0; kc < 8; kc++) {
                uint32_t bk[4];
                ldsm4(bk, bK + (kc * 16 + b_row) * 256 + co);
                mma_f16(S[2 * kc], qf[d], bk[0], bk[1]);
                mma_f16(S[2 * kc + 1], qf[d], bk[2], bk[3]);
            }
        }

        // ---- softmax: exp2 (Q pre-scaled by log2e) ----
        uint32_t ph[8][4];
#pragma unroll
        for (int kc = 0; kc < 8; kc++) {
            float* s0 = S[2 * kc];
            float* s1 = S[2 * kc + 1];
            float e00 = exp2f(s0[0]), e01 = exp2f(s0[1]);
            float e02 = exp2f(s0[2]), e03 = exp2f(s0[3]);
            float e10 = exp2f(s1[0]), e11 = exp2f(s1[1]);
            float e12 = exp2f(s1[2]), e13 = exp2f(s1[3]);
            l0 += e00 + e01 + e10 + e11;
            l1 += e02 + e03 + e12 + e13;
            ph[kc][0] = pkh(e00, e01); ph[kc][1] = pkh(e02, e03);
            ph[kc][2] = pkh(e10, e11); ph[kc][3] = pkh(e12, e13);
        }

        // ---- O += P V : kc-outer, nb-inner (16 chains) ----
#pragma unroll
        for (int kc = 0; kc < 8; kc++) {
            int ch = 2 * kc + b_ch;
            uint32_t co = ((ch & 8) | ((ch & 7) ^ lr)) << 4;
#pragma unroll
            for (int nb2 = 0; nb2 < 8; nb2++) {
                uint32_t bv[4];
                ldsm4(bv, bV + (nb2 * 16 + b_row) * 256 + co);
                mma_f16(O[2 * nb2], ph[kc], bv[0], bv[1]);
                mma_f16(O[2 * nb2 + 1], ph[kc], bv[2], bv[3]);
            }
        }
        __syncthreads();
        if (t + 2 < 32) {
            fillA((t & 1) ? bK1 : bK0, Kg + (size_t)(t + 2) * 128 * DEMB, DEMB);
            fillA((t & 1) ? bV1 : bV0, Vg + (t + 2) * 128, NPIX);
            CP_COMMIT();
        }
    }

#pragma unroll
    for (int off = 1; off < 4; off <<= 1) {
        l0 += __shfl_xor_sync(0xffffffffu, l0, off);
        l1 += __shfl_xor_sync(0xffffffffu, l1, off);
    }
    const float inv0 = 1.f / l0, inv1 = 1.f / l1;

    const int qg0 = qbase + q0 + (lane >> 2);
#pragma unroll
    for (int nb2 = 0; nb2 < 16; nb2++) {
        int d = nb2 * 8 + 2 * (lane & 3);
        Oh[(size_t)d * NPIX + qg0]           = __float2half_rn(O[nb2][0] * inv0);
        Oh[(size_t)(d + 1) * NPIX + qg0]     = __float2half_rn(O[nb2][1] * inv0);
        Oh[(size_t)d * NPIX + qg0 + 8]       = __float2half_rn(O[nb2][2] * inv1);
        Oh[(size_t)(d + 1) * NPIX + qg0 + 8] = __float2half_rn(O[nb2][3] * inv1);
    }
}

// ---------------- launch -----------------------------------------------------
extern "C" void kernel_launch(void* const* d_in, const int* in_sizes, int n_in,
                              void* d_out, int out_size)
{
    (void)in_sizes; (void)n_in; (void)out_size;
    const float* f_rgb   = (const float*)d_in[0];
    const float* f_pl    = (const float*)d_in[1];
    const float* w_q_rgb = (const float*)d_in[2];
    const float* b_q_rgb = (const float*)d_in[3];
    const float* w_k_pl  = (const float*)d_in[4];
    const float* b_k_pl  = (const float*)d_in[5];
    const float* w_v_pl  = (const float*)d_in[6];
    const float* b_v_pl  = (const float*)d_in[7];
    const float* w_q_pl  = (const float*)d_in[8];
    const float* b_q_pl  = (const float*)d_in[9];
    const float* w_k_rgb = (const float*)d_in[10];
    const float* b_k_rgb = (const float*)d_in[11];
    const float* w_v_rgb = (const float*)d_in[12];
    const float* b_v_rgb = (const float*)d_in[13];
    const float* w_proj  = (const float*)d_in[14];
    const float* bn_g    = (const float*)d_in[15];
    const float* bn_b    = (const float*)d_in[16];
    const float* bn_m    = (const float*)d_in[17];
    const float* bn_v    = (const float*)d_in[18];

    __half *hp, *xh, *xl, *wh, *wl;
    cudaGetSymbolAddress((void**)&hp, g_h);
    cudaGetSymbolAddress((void**)&xh, g_xh);
    cudaGetSymbolAddress((void**)&xl, g_xl);
    cudaGetSymbolAddress((void**)&wh, g_wh);
    cudaGetSymbolAddress((void**)&wl, g_wl);

    const int NX = NBATCH * 256 * NPIX;
    CvtTab ct;
    const float* srcs[9] = { f_rgb, f_pl, w_q_rgb, w_k_rgb, w_v_rgb,
                             w_k_pl, w_v_pl, w_q_pl, w_proj };
    int sizes[9] = { NX, NX, 32768, 32768, 32768, 32768, 32768, 32768, 65536 };
    __half* dhs[9] = { xh, xh + NX, wh, wh + 32768, wh + 65536,
                       wh + 98304, wh + 131072, wh + 163840, wh + 196608 };
    __half* dls[9] = { xl, xl + NX, wl, wl + 32768, wl + 65536,
                       wl + 98304, wl + 131072, wl + 163840, wl + 196608 };
    int off = 0;
    for (int i = 0; i < 9; i++) {
        ct.src[i] = srcs[i]; ct.dh[i] = dhs[i]; ct.dl[i] = dls[i];
        ct.blkoff[i] = off;
        off += sizes[i] / 2048;
    }
    ct.blkoff[9] = off;
    cvt_all<<<off, 256>>>(ct);

    const size_t PL = (size_t)NBATCH * DEMB * NPIX;
    ProjTab pt;
    int woffs[6] = { 0, 32768, 65536, 98304, 131072, 163840 };
    const float* biases[6] = { b_q_rgb, b_k_rgb, b_v_rgb, b_k_pl, b_v_pl, b_q_pl };
    float scales[6] = { ATT_SCALE * LOG2E, 1.f, 1.f, 1.f, 1.f, ATT_SCALE * LOG2E };
    int vmodes[6] = { 0, 0, 1, 0, 1, 0 };
    int planes[6] = { 0, 4, 5, 1, 2, 3 };  // Qa, Kb, Vb, Ka, Va, Qb
    for (int i = 0; i < 6; i++) {
        pt.woff[i] = woffs[i]; pt.bias[i] = biases[i];
        pt.scale[i] = scales[i]; pt.vmode[i] = vmodes[i];
        pt.out[i] = hp + (size_t)planes[i] * PL;
    }

    cudaFuncSetAttribute(proj_mma, cudaFuncAttributeMaxDynamicSharedMemorySize, GEMM_SMEM);
    proj_mma<<<dim3(32, 3, 16), 256, GEMM_SMEM>>>(pt);

    cudaFuncSetAttribute(attn_kernel, cudaFuncAttributeMaxDynamicSharedMemorySize, ATT_SMEM);
    attn_kernel<<<dim3(NPIX / 64, 2, NBATCH), 128, ATT_SMEM>>>();

    cudaFuncSetAttribute(final_mma, cudaFuncAttributeMaxDynamicSharedMemorySize, FINAL_SMEM);
    final_mma<<<dim3(32, 2, NBATCH), 256, FINAL_SMEM>>>((float*)d_out,
                                                        bn_g, bn_b, bn_m, bn_v);
}

// round 9
// speedup vs baseline: 8.4477x; 1.1896x over previous
#include <cuda_runtime.h>
#include <cuda_fp16.h>
#include <stdint.h>
#include <math.h>

#define NBATCH 8
#define NPIX   4096
#define DEMB   128
#define ATT_SCALE 0.08838834764831845f
#define LOG2E 1.4426950408889634f
#define BN_EPS 1e-5f

// fp16 planes for attention operands: (dir*3+kind), kind 0 Q,1 K,2 V.
// Q,K stored [n][d]; V stored [d][n]. Q pre-scaled by ATT_SCALE*LOG2E.
__device__ __half g_h[(size_t)6 * NBATCH * DEMB * NPIX];        // 50 MB
// input features fp16, layout [input][b][k=256][n=4096]
__device__ __half g_x[(size_t)2 * NBATCH * 256 * NPIX];         // 16.8 MB
// attention output (concat) fp16 [b][256][4096]
__device__ __half g_ch[(size_t)NBATCH * 256 * NPIX];            // 16.8 MB
// weights fp16: 6 proj W [128][256] at p*32768, then w_proj [256][256] at 196608
__device__ __half g_w[262144];

// ------------------------------------------------------------- helpers -----
__device__ __forceinline__ uint32_t smem_u32(const void* p) {
    uint32_t a;
    asm("{ .reg .u64 t; cvta.to.shared.u64 t, %1; cvt.u32.u64 %0, t; }" : "=r"(a) : "l"(p));
    return a;
}
__device__ __forceinline__ uint32_t pkh(float a, float b) {
    __half2 h = __floats2half2_rn(a, b);
    return *reinterpret_cast<uint32_t*>(&h);
}
__device__ __forceinline__ float ex2(float x) {
    float r;
    asm("ex2.approx.ftz.f32 %0, %1;" : "=f"(r) : "f"(x));
    return r;
}
__device__ __forceinline__ void mma_f16(float c[4], const uint32_t a[4],
                                        uint32_t b0, uint32_t b1) {
    asm volatile("mma.sync.aligned.m16n8k16.row.col.f32.f16.f16.f32 "
        "{%0,%1,%2,%3}, {%4,%5,%6,%7}, {%8,%9}, {%0,%1,%2,%3};"
        : "+f"(c[0]), "+f"(c[1]), "+f"(c[2]), "+f"(c[3])
        : "r"(a[0]), "r"(a[1]), "r"(a[2]), "r"(a[3]), "r"(b0), "r"(b1));
}
__device__ __forceinline__ void ldsm4(uint32_t r[4], uint32_t addr) {
    asm volatile("ldmatrix.sync.aligned.m8n8.x4.shared.b16 {%0,%1,%2,%3}, [%4];"
        : "=r"(r[0]), "=r"(r[1]), "=r"(r[2]), "=r"(r[3]) : "r"(addr));
}
__device__ __forceinline__ void ldsm4t(uint32_t r[4], uint32_t addr) {
    asm volatile("ldmatrix.sync.aligned.m8n8.x4.trans.shared.b16 {%0,%1,%2,%3}, [%4];"
        : "=r"(r[0]), "=r"(r[1]), "=r"(r[2]), "=r"(r[3]) : "r"(addr));
}
__device__ __forceinline__ void cpa16(uint32_t s, const void* g) {
    asm volatile("cp.async.cg.shared.global [%0], [%1], 16;" :: "r"(s), "l"(g));
}
#define CP_COMMIT() asm volatile("cp.async.commit_group;" ::: "memory")
#define CP_WAIT(n)  asm volatile("cp.async.wait_group %0;" :: "n"(n) : "memory")

// ---------------- merged fp32 -> fp16 converter -----------------------------
struct CvtTab {
    const float* src[9];
    __half* dst[9];
    int blkoff[10];     // block-index prefix (2048 elems per block)
};

__global__ __launch_bounds__(256) void cvt_all(CvtTab t)
{
    int blk = blockIdx.x, seg = 0;
    while (blk >= t.blkoff[seg + 1]) seg++;
    int i = ((blk - t.blkoff[seg]) * 256 + threadIdx.x) * 8;
    const float* src = t.src[seg];
    __half* dst = t.dst[seg];

    float4 a = *(const float4*)(src + i);
    float4 b = *(const float4*)(src + i + 4);
    uint2 o0 = make_uint2(pkh(a.x, a.y), pkh(a.z, a.w));
    uint2 o1 = make_uint2(pkh(b.x, b.y), pkh(b.z, b.w));
    *(uint2*)(dst + i) = o0;
    *(uint2*)(dst + i + 4) = o1;
}

// ---------------- 1-term fp16 GEMM constants (K-chunk 32) -------------------
#define FB_XH 0
#define FB_WH 8704
#define FB_BUF 18944
#define GEMM_SMEM 37888     // 2 bufs; epilogue stage (<=34816B) reuses them

struct ProjTab {
    int woff[6];
    const float* bias[6];
    float scale[6];
    int vmode[6];           // 0: out [n][d], 1: out [d][n]
    __half* out[6];
};

// proj: Y(128, 4096-tile) = W(128,256) @ X(256,4096) + bias, fp16 out planes
__global__ __launch_bounds__(256, 2) void proj_mma(ProjTab pt)
{
    extern __shared__ char sm[];
    const int tid = threadIdx.x, lane = tid & 31, w = tid >> 5;
    const int nb = blockIdx.x * 128;
    const int input = blockIdx.z >> 3, b = blockIdx.z & 7;
    const int p = input * 3 + blockIdx.y;

    const __half* Xh = g_x + (size_t)(input * 8 + b) * 256 * NPIX;
    const __half* Wh = g_w + pt.woff[p];
    const float* bias = pt.bias[p];
    const float scale = pt.scale[p];
    const int vmode = pt.vmode[p];
    __half* out = pt.out[p] + (size_t)b * DEMB * NPIX;

    const uint32_t sb = smem_u32(sm);

    auto fill = [&](int c, int s) {
        uint32_t base = sb + s * FB_BUF;
#pragma unroll
        for (int i = 0; i < 2; i++) {   // X: 32 rows x 16 chunks
            int idx = tid + 256 * i, r = idx >> 4, ch = idx & 15;
            cpa16(base + FB_XH + r * 272 + ch * 16,
                  Xh + (size_t)(c * 32 + r) * NPIX + nb + ch * 8);
        }
#pragma unroll
        for (int i = 0; i < 2; i++) {   // W: 128 rows x 4 chunks
            int idx = tid + 256 * i, m = idx >> 2, ch = idx & 3;
            cpa16(base + FB_WH + m * 80 + ch * 16,
                  Wh + (size_t)m * 256 + c * 32 + ch * 8);
        }
    };

    fill(0, 0); CP_COMMIT();
    fill(1, 1); CP_COMMIT();

    const int lr = lane & 7, g = lane >> 3;
    const int fr = lr + ((g & 1) << 3), fc = g >> 1;
    const int wm = w >> 2, wn = w & 3;

    float C[4][4][4];
#pragma unroll
    for (int i = 0; i < 4; i++)
#pragma unroll
        for (int j = 0; j < 4; j++)
#pragma unroll
            for (int k = 0; k < 4; k++) C[i][j][k] = 0.f;

    for (int c = 0; c < 8; c++) {
        if (c < 6) { CP_WAIT(1); } else { CP_WAIT(0); }
        __syncthreads();
        const uint32_t base = sb + (c & 1) * FB_BUF;
#pragma unroll
        for (int kt = 0; kt < 2; kt++) {
            uint32_t bh[2][4];
#pragma unroll
            for (int nh = 0; nh < 2; nh++)
                ldsm4t(bh[nh], base + FB_XH + (kt * 16 + fr) * 272 +
                               (wn * 32 + nh * 16 + fc * 8) * 2);
#pragma unroll
            for (int mt = 0; mt < 4; mt++) {
                uint32_t ah[4];
                ldsm4(ah, base + FB_WH + (wm * 64 + mt * 16 + fr) * 80 +
                          (kt * 16 + fc * 8) * 2);
#pragma unroll
                for (int nh = 0; nh < 2; nh++) {
                    mma_f16(C[mt][2 * nh], ah, bh[nh][0], bh[nh][1]);
                    mma_f16(C[mt][2 * nh + 1], ah, bh[nh][2], bh[nh][3]);
                }
            }
        }
        __syncthreads();
        if (c + 2 < 8) { fill(c + 2, c & 1); CP_COMMIT(); }
    }

    // epilogue: bias+scale, fp16, stage to target layout (pitch 272B)
    __half* stage = (__half*)sm;
#pragma unroll
    for (int mt = 0; mt < 4; mt++) {
        int m0 = wm * 64 + mt * 16 + (lane >> 2);
        float b0 = bias[m0], b1 = bias[m0 + 8];
#pragma unroll
        for (int nt = 0; nt < 4; nt++) {
            int n = wn * 32 + nt * 8 + 2 * (lane & 3);
            float v0 = (C[mt][nt][0] + b0) * scale;
            float v1 = (C[mt][nt][1] + b0) * scale;
            float v2 = (C[mt][nt][2] + b1) * scale;
            float v3 = (C[mt][nt][3] + b1) * scale;
            if (vmode == 0) {   // stage [n][d]
                stage[n * 136 + m0] = __float2half_rn(v0);
                stage[(n + 1) * 136 + m0] = __float2half_rn(v1);
                stage[n * 136 + m0 + 8] = __float2half_rn(v2);
                stage[(n + 1) * 136 + m0 + 8] = __float2half_rn(v3);
            } else {            // stage [d][n]
                *(uint32_t*)&stage[m0 * 136 + n] = pkh(v0, v1);
                *(uint32_t*)&stage[(m0 + 8) * 136 + n] = pkh(v2, v3);
            }
        }
    }
    __syncthreads();
#pragma unroll
    for (int i = 0; i < 8; i++) {
        int idx = tid + 256 * i, r = idx >> 4, ch = idx & 15;
        uint4 v = *(uint4*)((char*)sm + r * 272 + ch * 16);
        if (vmode == 0)
            *(uint4*)(out + (size_t)(nb + r) * DEMB + ch * 8) = v;
        else
            *(uint4*)(out + (size_t)r * NPIX + nb + ch * 8) = v;
    }
}

// ---------------- final GEMM (1-term fp16): out = relu(BN(Wp @ comb)) -------
#define FINAL_SMEM 67584    // epilogue stage (128 rows x 528B) dominates

__global__ __launch_bounds__(256, 2) void final_mma(
    float* __restrict__ Y,
    const float* __restrict__ bng, const float* __restrict__ bnb,
    const float* __restrict__ bnm, const float* __restrict__ bnv)
{
    extern __shared__ char sm[];
    const int tid = threadIdx.x, lane = tid & 31, w = tid >> 5;
    const int nb = blockIdx.x * 128;
    const int mbase = blockIdx.y * 128;
    const int b = blockIdx.z;

    const __half* Xh = g_ch + (size_t)b * 256 * NPIX;
    const __half* Wh = g_w + 196608;
    float* Yb = Y + (size_t)b * 256 * NPIX;

    const uint32_t sb = smem_u32(sm);

    auto fill = [&](int c, int s) {
        uint32_t base = sb + s * FB_BUF;
#pragma unroll
        for (int i = 0; i < 2; i++) {
            int idx = tid + 256 * i, r = idx >> 4, ch = idx & 15;
            cpa16(base + FB_XH + r * 272 + ch * 16,
                  Xh + (size_t)(c * 32 + r) * NPIX + nb + ch * 8);
        }
#pragma unroll
        for (int i = 0; i < 2; i++) {
            int idx = tid + 256 * i, m = idx >> 2, ch = idx & 3;
            cpa16(base + FB_WH + m * 80 + ch * 16,
                  Wh + (size_t)(mbase + m) * 256 + c * 32 + ch * 8);
        }
    };

    fill(0, 0); CP_COMMIT();
    fill(1, 1); CP_COMMIT();

    const int lr = lane & 7, g = lane >> 3;
    const int fr = lr + ((g & 1) << 3), fc = g >> 1;
    const int wm = w >> 2, wn = w & 3;

    float C[4][4][4];
#pragma unroll
    for (int i = 0; i < 4; i++)
#pragma unroll
        for (int j = 0; j < 4; j++)
#pragma unroll
            for (int k = 0; k < 4; k++) C[i][j][k] = 0.f;

    for (int c = 0; c < 8; c++) {
        if (c < 6) { CP_WAIT(1); } else { CP_WAIT(0); }
        __syncthreads();
        const uint32_t base = sb + (c & 1) * FB_BUF;
#pragma unroll
        for (int kt = 0; kt < 2; kt++) {
            uint32_t bh[2][4];
#pragma unroll
            for (int nh = 0; nh < 2; nh++)
                ldsm4t(bh[nh], base + FB_XH + (kt * 16 + fr) * 272 +
                               (wn * 32 + nh * 16 + fc * 8) * 2);
#pragma unroll
            for (int mt = 0; mt < 4; mt++) {
                uint32_t ah[4];
                ldsm4(ah, base + FB_WH + (wm * 64 + mt * 16 + fr) * 80 +
                          (kt * 16 + fc * 8) * 2);
#pragma unroll
                for (int nh = 0; nh < 2; nh++) {
                    mma_f16(C[mt][2 * nh], ah, bh[nh][0], bh[nh][1]);
                    mma_f16(C[mt][2 * nh + 1], ah, bh[nh][2], bh[nh][3]);
                }
            }
        }
        __syncthreads();
        if (c + 2 < 8) { fill(c + 2, c & 1); CP_COMMIT(); }
    }

    // BN + ReLU, stage fp32 [m][n] pitch 132 floats, coalesced STG
    float* stage = (float*)sm;
#pragma unroll
    for (int mt = 0; mt < 4; mt++) {
        int ml = wm * 64 + mt * 16 + (lane >> 2);
        int m0 = mbase + ml, m1 = m0 + 8;
        float i0 = bng[m0] * rsqrtf(bnv[m0] + BN_EPS);
        float s0 = bnb[m0] - bnm[m0] * i0;
        float i1 = bng[m1] * rsqrtf(bnv[m1] + BN_EPS);
        float s1 = bnb[m1] - bnm[m1] * i1;
#pragma unroll
        for (int nt = 0; nt < 4; nt++) {
            int n = wn * 32 + nt * 8 + 2 * (lane & 3);
            stage[ml * 132 + n]       = fmaxf(fmaf(C[mt][nt][0], i0, s0), 0.f);
            stage[ml * 132 + n + 1]   = fmaxf(fmaf(C[mt][nt][1], i0, s0), 0.f);
            stage[(ml + 8) * 132 + n]     = fmaxf(fmaf(C[mt][nt][2], i1, s1), 0.f);
            stage[(ml + 8) * 132 + n + 1] = fmaxf(fmaf(C[mt][nt][3], i1, s1), 0.f);
        }
    }
    __syncthreads();
#pragma unroll
    for (int i = 0; i < 16; i++) {
        int idx = tid + 256 * i, r = idx >> 5, ch = idx & 31;
        float4 v = *(float4*)((char*)sm + r * 528 + ch * 16);
        *(float4*)&Yb[(size_t)(mbase + r) * NPIX + nb + ch * 4] = v;
    }
}

// ---------------- flash attention: BQ=64, 256 threads, key-split warps ------
// warps: slab = w&3 (16-q slab), khalf = w>>2 (64-key half of each 128-key tile)
// smem: Q 16KB | K0 K1 V0 V1 32KB each = 144KB; 1 CTA/SM, grid 1024 (~7 waves)
#define ATT_SMEM (16384 + 4 * 32768)

__global__ __launch_bounds__(256, 1) void attn_kernel()
{
    extern __shared__ char sm[];
    const int tid = threadIdx.x, lane = tid & 31, w = tid >> 5;
    const int slab = w & 3, khalf = w >> 2;
    const int qt = blockIdx.x, dir = blockIdx.y, b = blockIdx.z;
    const int qbase = qt * 64;
    const size_t PLANE = (size_t)DEMB * NPIX;

    const __half* Qg = g_h + ((size_t)(dir * 3 + 0) * NBATCH + b) * PLANE;
    const __half* Kg = g_h + ((size_t)(dir * 3 + 1) * NBATCH + b) * PLANE;
    const __half* Vg = g_h + ((size_t)(dir * 3 + 2) * NBATCH + b) * PLANE;
    __half* Oh = g_ch + ((size_t)b * 256 + dir * 128) * NPIX;

    const uint32_t bQ = smem_u32(sm);
    const uint32_t bK0 = bQ + 16384, bK1 = bQ + 49152;
    const uint32_t bV0 = bQ + 81920, bV1 = bQ + 114688;

    // 128x128 tile fill, 16B-chunk XOR swizzle (256 threads, 8 iters)
    auto fillA = [&](uint32_t dst, const __half* src, int rstride) {
#pragma unroll
        for (int i = 0; i < 8; i++) {
            int idx = tid + 256 * i;
            int r = idx >> 4, c = idx & 15;
            int ch = (c & 8) | ((c & 7) ^ (r & 7));
            cpa16(dst + r * 256 + ch * 16, src + (size_t)r * rstride + c * 8);
        }
    };
    auto fillQ = [&]() {
#pragma unroll
        for (int i = 0; i < 4; i++) {
            int idx = tid + 256 * i;
            int r = idx >> 4, c = idx & 15;
            int ch = (c & 8) | ((c & 7) ^ (r & 7));
            cpa16(bQ + r * 256 + ch * 16, Qg + (size_t)(qbase + r) * DEMB + c * 8);
        }
    };

    fillQ();                                              CP_COMMIT();
    fillA(bK0, Kg, DEMB); fillA(bV0, Vg, NPIX);           CP_COMMIT();
    fillA(bK1, Kg + (size_t)128 * DEMB, DEMB);
    fillA(bV1, Vg + 128, NPIX);                           CP_COMMIT();

    const int lr = lane & 7, g = lane >> 3;
    const int a_row = lr + ((g & 1) << 3), a_ch = g >> 1;
    const int b_row = lr + ((g >> 1) << 3), b_ch = g & 1;
    const int q0 = 16 * slab;

    CP_WAIT(2);
    __syncthreads();

    uint32_t qf[8][4];
#pragma unroll
    for (int k = 0; k < 8; k++) {
        int ch = 2 * k + a_ch;
        ldsm4(qf[k], bQ + (q0 + a_row) * 256 + (((ch & 8) | ((ch & 7) ^ lr)) << 4));
    }

    float O[16][4];
#pragma unroll
    for (int i = 0; i < 16; i++)
#pragma unroll
        for (int j = 0; j < 4; j++) O[i][j] = 0.f;
    float l0 = 0.f, l1 = 0.f;

    for (int t = 0; t < 32; t++) {
        if (t < 30) { CP_WAIT(1); } else { CP_WAIT(0); }
        __syncthreads();
        const uint32_t bK = (t & 1) ? bK1 : bK0;
        const uint32_t bV = (t & 1) ? bV1 : bV0;

        // ---- S (16q x 64 keys of this half): d-outer, kc-inner -> 8 chains --
        float S[8][4];
#pragma unroll
        for (int i = 0; i < 8; i++)
#pragma unroll
            for (int j = 0; j < 4; j++) S[i][j] = 0.f;
#pragma unroll
        for (int d = 0; d < 8; d++) {
            int ch = 2 * d + b_ch;
            uint32_t co = ((ch & 8) | ((ch & 7) ^ lr)) << 4;
#pragma unroll
            for (int kc = 0; kc < 4; kc++) {
                uint32_t bk[4];
                ldsm4(bk, bK + ((khalf * 4 + kc) * 16 + b_row) * 256 + co);
                mma_f16(S[2 * kc], qf[d], bk[0], bk[1]);
                mma_f16(S[2 * kc + 1], qf[d], bk[2], bk[3]);
            }
        }

        // ---- softmax: raw MUFU ex2 (Q pre-scaled by log2e) ----
        uint32_t ph[4][4];
#pragma unroll
        for (int kc = 0; kc < 4; kc++) {
            float* s0 = S[2 * kc];
            float* s1 = S[2 * kc + 1];
            float e00 = ex2(s0[0]), e01 = ex2(s0[1]);
            float e02 = ex2(s0[2]), e03 = ex2(s0[3]);
            float e10 = ex2(s1[0]), e11 = ex2(s1[1]);
            float e12 = ex2(s1[2]), e13 = ex2(s1[3]);
            l0 += e00 + e01 + e10 + e11;
            l1 += e02 + e03 + e12 + e13;
            ph[kc][0] = pkh(e00, e01); ph[kc][1] = pkh(e02, e03);
            ph[kc][2] = pkh(e10, e11); ph[kc][3] = pkh(e12, e13);
        }

        // ---- O += P V over this key half: kc-outer, nb-inner (16 chains) ----
#pragma unroll
        for (int kc = 0; kc < 4; kc++) {
            int ch = 2 * (khalf * 4 + kc) + b_ch;
            uint32_t co = ((ch & 8) | ((ch & 7) ^ lr)) << 4;
#pragma unroll
            for (int nb2 = 0; nb2 < 8; nb2++) {
                uint32_t bv[4];
                ldsm4(bv, bV + (nb2 * 16 + b_row) * 256 + co);
                mma_f16(O[2 * nb2], ph[kc], bv[0], bv[1]);
                mma_f16(O[2 * nb2 + 1], ph[kc], bv[2], bv[3]);
            }
        }
        __syncthreads();
        if (t + 2 < 32) {
            fillA((t & 1) ? bK1 : bK0, Kg + (size_t)(t + 2) * 128 * DEMB, DEMB);
            fillA((t & 1) ? bV1 : bV0, Vg + (t + 2) * 128, NPIX);
            CP_COMMIT();
        }
    }

    // quad-reduce l over the 16-key column groups this warp saw
#pragma unroll
    for (int off = 1; off < 4; off <<= 1) {
        l0 += __shfl_xor_sync(0xffffffffu, l0, off);
        l1 += __shfl_xor_sync(0xffffffffu, l1, off);
    }

    // cross-warp (key-half) reduce through smem, then store
    float* sO = (float*)(sm + 16384);          // 64 rows x pitch 132 fp32
    float* sL = (float*)(sm + 16384 + 34048);  // 64 floats
    const int row0 = slab * 16 + (lane >> 2);
    __syncthreads();
    if (khalf == 1) {
        if ((lane & 3) == 0) { sL[row0] = l0; sL[row0 + 8] = l1; }
#pragma unroll
        for (int nb2 = 0; nb2 < 16; nb2++) {
            int d = nb2 * 8 + 2 * (lane & 3);
            sO[row0 * 132 + d] = O[nb2][0];
            sO[row0 * 132 + d + 1] = O[nb2][1];
            sO[(row0 + 8) * 132 + d] = O[nb2][2];
            sO[(row0 + 8) * 132 + d + 1] = O[nb2][3];
        }
    }
    __syncthreads();
    if (khalf == 0) {
        l0 += sL[row0];
        l1 += sL[row0 + 8];
        const float inv0 = 1.f / l0, inv1 = 1.f / l1;
        const int qg0 = qbase + row0;
#pragma unroll
        for (int nb2 = 0; nb2 < 16; nb2++) {
            int d = nb2 * 8 + 2 * (lane & 3);
            float v0 = (O[nb2][0] + sO[row0 * 132 + d]) * inv0;
            float v1 = (O[nb2][1] + sO[row0 * 132 + d + 1]) * inv0;
            float v2 = (O[nb2][2] + sO[(row0 + 8) * 132 + d]) * inv1;
            float v3 = (O[nb2][3] + sO[(row0 + 8) * 132 + d + 1]) * inv1;
            Oh[(size_t)d * NPIX + qg0]           = __float2half_rn(v0);
            Oh[(size_t)(d + 1) * NPIX + qg0]     = __float2half_rn(v1);
            Oh[(size_t)d * NPIX + qg0 + 8]       = __float2half_rn(v2);
            Oh[(size_t)(d + 1) * NPIX + qg0 + 8] = __float2half_rn(v3);
        }
    }
}

// ---------------- launch -----------------------------------------------------
extern "C" void kernel_launch(void* const* d_in, const int* in_sizes, int n_in,
                              void* d_out, int out_size)
{
    (void)in_sizes; (void)n_in; (void)out_size;
    const float* f_rgb   = (const float*)d_in[0];
    const float* f_pl    = (const float*)d_in[1];
    const float* w_q_rgb = (const float*)d_in[2];
    const float* b_q_rgb = (const float*)d_in[3];
    const float* w_k_pl  = (const float*)d_in[4];
    const float* b_k_pl  = (const float*)d_in[5];
    const float* w_v_pl  = (const float*)d_in[6];
    const float* b_v_pl  = (const float*)d_in[7];
    const float* w_q_pl  = (const float*)d_in[8];
    const float* b_q_pl  = (const float*)d_in[9];
    const float* w_k_rgb = (const float*)d_in[10];
    const float* b_k_rgb = (const float*)d_in[11];
    const float* w_v_rgb = (const float*)d_in[12];
    const float* b_v_rgb = (const float*)d_in[13];
    const float* w_proj  = (const float*)d_in[14];
    const float* bn_g    = (const float*)d_in[15];
    const float* bn_b    = (const float*)d_in[16];
    const float* bn_m    = (const float*)d_in[17];
    const float* bn_v    = (const float*)d_in[18];

    __half *hp, *xp, *wp;
    cudaGetSymbolAddress((void**)&hp, g_h);
    cudaGetSymbolAddress((void**)&xp, g_x);
    cudaGetSymbolAddress((void**)&wp, g_w);

    const int NX = NBATCH * 256 * NPIX;
    CvtTab ct;
    const float* srcs[9] = { f_rgb, f_pl, w_q_rgb, w_k_rgb, w_v_rgb,
                             w_k_pl, w_v_pl, w_q_pl, w_proj };
    int sizes[9] = { NX, NX, 32768, 32768, 32768, 32768, 32768, 32768, 65536 };
    __half* dsts[9] = { xp, xp + NX, wp, wp + 32768, wp + 65536,
                        wp + 98304, wp + 131072, wp + 163840, wp + 196608 };
    int off = 0;
    for (int i = 0; i < 9; i++) {
        ct.src[i] = srcs[i]; ct.dst[i] = dsts[i];
        ct.blkoff[i] = off;
        off += sizes[i] / 2048;
    }
    ct.blkoff[9] = off;
    cvt_all<<<off, 256>>>(ct);

    const size_t PL = (size_t)NBATCH * DEMB * NPIX;
    ProjTab pt;
    int woffs[6] = { 0, 32768, 65536, 98304, 131072, 163840 };
    const float* biases[6] = { b_q_rgb, b_k_rgb, b_v_rgb, b_k_pl, b_v_pl, b_q_pl };
    float scales[6] = { ATT_SCALE * LOG2E, 1.f, 1.f, 1.f, 1.f, ATT_SCALE * LOG2E };
    int vmodes[6] = { 0, 0, 1, 0, 1, 0 };
    int planes[6] = { 0, 4, 5, 1, 2, 3 };  // Qa, Kb, Vb, Ka, Va, Qb
    for (int i = 0; i < 6; i++) {
        pt.woff[i] = woffs[i]; pt.bias[i] = biases[i];
        pt.scale[i] = scales[i]; pt.vmode[i] = vmodes[i];
        pt.out[i] = hp + (size_t)planes[i] * PL;
    }

    cudaFuncSetAttribute(proj_mma, cudaFuncAttributeMaxDynamicSharedMemorySize, GEMM_SMEM);
    proj_mma<<<dim3(32, 3, 16), 256, GEMM_SMEM>>>(pt);

    cudaFuncSetAttribute(attn_kernel, cudaFuncAttributeMaxDynamicSharedMemorySize, ATT_SMEM);
    attn_kernel<<<dim3(NPIX / 64, 2, NBATCH), 256, ATT_SMEM>>>();

    cudaFuncSetAttribute(final_mma, cudaFuncAttributeMaxDynamicSharedMemorySize, FINAL_SMEM);
    final_mma<<<dim3(32, 2, NBATCH), 256, FINAL_SMEM>>>((float*)d_out,
                                                        bn_g, bn_b, bn_m, bn_v);
}